// round 5
// baseline (speedup 1.0000x reference)
#include <cuda_runtime.h>
#include <cuda_bf16.h>
#include <cuda_fp16.h>
#include <cstdint>

// Problem constants
#define BZ 2
#define SQ 2048
#define DH 1024
#define NH 16
#define HDIM 64

// 0.125 * log2(e): folded into Q so softmax runs in the exp2 domain
#define SCALE_LOG2 0.18033688011112042f

// ---------------------------------------------------------------------------
// Scratch (no cudaMalloc allowed)
// ---------------------------------------------------------------------------
__device__ __align__(16) float g_qkv[(size_t)BZ * SQ * 3 * DH];   // [2,2048,3072]
__device__ __align__(16) __nv_bfloat16 g_xh[(size_t)BZ * SQ * DH];
__device__ __align__(16) __nv_bfloat16 g_xl[(size_t)BZ * SQ * DH];
__device__ __align__(16) __nv_bfloat16 g_wqh[(size_t)3 * DH * DH];
__device__ __align__(16) __nv_bfloat16 g_wql[(size_t)3 * DH * DH];
__device__ __align__(16) __nv_bfloat16 g_woh[(size_t)DH * DH];
__device__ __align__(16) __nv_bfloat16 g_wol[(size_t)DH * DH];
// head-major attention operands (fp16)
__device__ __align__(16) __half g_Qh[(size_t)BZ * NH * SQ * HDIM];
__device__ __align__(16) __half g_Ql[(size_t)BZ * NH * SQ * HDIM];
__device__ __align__(16) __half g_Kf[(size_t)BZ * NH * SQ * HDIM];
__device__ __align__(16) __half g_Vth[(size_t)BZ * NH * HDIM * SQ];
__device__ __align__(16) __half g_Vtl[(size_t)BZ * NH * HDIM * SQ];
// attention output (bf16 split, [b,s,1024])
__device__ __align__(16) __nv_bfloat16 g_ah[(size_t)BZ * SQ * DH];
__device__ __align__(16) __nv_bfloat16 g_al[(size_t)BZ * SQ * DH];

// ---------------------------------------------------------------------------
// Portable PTX helpers (sm_80+ subset; no arch-"a" features)
// ---------------------------------------------------------------------------
__device__ __forceinline__ uint32_t smem_to_u32(const void* p) {
    uint32_t a;
    asm("{ .reg .u64 t; cvta.to.shared.u64 t, %1; cvt.u32.u64 %0, t; }"
        : "=r"(a) : "l"(p));
    return a;
}

__device__ __forceinline__ void cp16(uint32_t saddr, const void* gaddr) {
    asm volatile("cp.async.cg.shared.global [%0], [%1], 16;"
                 :: "r"(saddr), "l"(gaddr));
}
#define CP_COMMIT() asm volatile("cp.async.commit_group;" ::: "memory")
#define CP_WAIT(n)  asm volatile("cp.async.wait_group %0;" :: "n"(n) : "memory")

__device__ __forceinline__ void ldmx4(uint32_t* r, uint32_t addr) {
    asm volatile("ldmatrix.sync.aligned.m8n8.x4.shared.b16 {%0,%1,%2,%3}, [%4];"
                 : "=r"(r[0]), "=r"(r[1]), "=r"(r[2]), "=r"(r[3]) : "r"(addr));
}

__device__ __forceinline__ void mma_bf16(float* d, const uint32_t* a,
                                         uint32_t b0, uint32_t b1) {
    asm volatile(
        "mma.sync.aligned.m16n8k16.row.col.f32.bf16.bf16.f32 "
        "{%0,%1,%2,%3}, {%4,%5,%6,%7}, {%8,%9}, {%0,%1,%2,%3};"
        : "+f"(d[0]), "+f"(d[1]), "+f"(d[2]), "+f"(d[3])
        : "r"(a[0]), "r"(a[1]), "r"(a[2]), "r"(a[3]), "r"(b0), "r"(b1));
}

__device__ __forceinline__ void mma_f16(float* d, const uint32_t* a,
                                        uint32_t b0, uint32_t b1) {
    asm volatile(
        "mma.sync.aligned.m16n8k16.row.col.f32.f16.f16.f32 "
        "{%0,%1,%2,%3}, {%4,%5,%6,%7}, {%8,%9}, {%0,%1,%2,%3};"
        : "+f"(d[0]), "+f"(d[1]), "+f"(d[2]), "+f"(d[3])
        : "r"(a[0]), "r"(a[1]), "r"(a[2]), "r"(a[3]), "r"(b0), "r"(b1));
}

__device__ __forceinline__ float ex2f(float x) {
    float r;
    asm("ex2.approx.f32 %0, %1;" : "=f"(r) : "f"(x));
    return r;
}
// {lo16 = hi-bf16 of a, hi16 = hi-bf16 of b}  (truncation split)
__device__ __forceinline__ uint32_t prmt_hi2(uint32_t a, uint32_t b) {
    uint32_t d;
    asm("prmt.b32 %0, %1, %2, 0x7632;" : "=r"(d) : "r"(a), "r"(b));
    return d;
}
// pack {lo16 = bf16(lo_elem), hi16 = bf16(hi_elem)} round-to-nearest
__device__ __forceinline__ uint32_t packbf2(float hi_elem, float lo_elem) {
    uint32_t d;
    asm("cvt.rn.bf16x2.f32 %0, %1, %2;" : "=r"(d) : "f"(hi_elem), "f"(lo_elem));
    return d;
}

__device__ __forceinline__ void split4(float4 v, uint2& hi, uint2& lo) {
    union { __nv_bfloat16 b[4]; uint2 u; } H, L;
    float f[4] = {v.x, v.y, v.z, v.w};
    #pragma unroll
    for (int j = 0; j < 4; j++) {
        __nv_bfloat16 h = __float2bfloat16(f[j]);
        H.b[j] = h;
        L.b[j] = __float2bfloat16(f[j] - __bfloat162float(h));
    }
    hi = H.u; lo = L.u;
}

__device__ __forceinline__ void split4h(float4 v, uint2& hi, uint2& lo) {
    union { __half b[4]; uint2 u; } H, L;
    float f[4] = {v.x, v.y, v.z, v.w};
    #pragma unroll
    for (int j = 0; j < 4; j++) {
        __half h = __float2half_rn(f[j]);
        H.b[j] = h;
        L.b[j] = __float2half_rn(f[j] - __half2float(h));
    }
    hi = H.u; lo = L.u;
}

__device__ __forceinline__ uint2 pack4h(float4 v) {
    union { __half b[4]; uint2 u; } H;
    H.b[0] = __float2half_rn(v.x);
    H.b[1] = __float2half_rn(v.y);
    H.b[2] = __float2half_rn(v.z);
    H.b[3] = __float2half_rn(v.w);
    return H.u;
}

// ---------------------------------------------------------------------------
// fp32 -> bf16 hi/lo split (4 elems/thread)
// ---------------------------------------------------------------------------
__global__ void split_hl(const float4* __restrict__ x,
                         uint2* __restrict__ hi, uint2* __restrict__ lo, int n4) {
    int i = blockIdx.x * blockDim.x + threadIdx.x;
    if (i >= n4) return;
    uint2 H, L;
    split4(x[i], H, L);
    hi[i] = H; lo[i] = L;
}

// ---------------------------------------------------------------------------
// prep_qkv: qkv fp32 [b,s,3072] -> head-major fp16:
//   Q*(0.125*log2e) split hi/lo -> [bh,s,64]; K plain -> [bh,s,64];
//   V^T split hi/lo -> [bh,64,s]
// ---------------------------------------------------------------------------
__global__ void prep_qkv(const float* __restrict__ qkv,
                         uint2* __restrict__ Qh, uint2* __restrict__ Ql,
                         uint2* __restrict__ Kf,
                         uint2* __restrict__ Vth, uint2* __restrict__ Vtl) {
    __shared__ float Vs[64][65];
    const int bh = blockIdx.y;
    const int b = bh >> 4, h = bh & 15;
    const int s0 = blockIdx.x * 64;
    const int tid = threadIdx.x;

    #pragma unroll
    for (int it = 0; it < 4; it++) {
        int lin = it * 256 + tid;
        int row = lin >> 4;     // 0..63
        int c4 = lin & 15;
        const float* base = qkv + ((size_t)(b * SQ + s0 + row)) * (3 * DH)
                                + h * HDIM + c4 * 4;
        float4 q = *(const float4*)base;
        float4 k = *(const float4*)(base + DH);
        float4 v = *(const float4*)(base + 2 * DH);
        q.x *= SCALE_LOG2; q.y *= SCALE_LOG2; q.z *= SCALE_LOG2; q.w *= SCALE_LOG2;
        uint2 H, L;
        size_t qi = (((size_t)bh * SQ + s0 + row) * HDIM + c4 * 4) >> 2;
        split4h(q, H, L); Qh[qi] = H; Ql[qi] = L;
        Kf[qi] = pack4h(k);
        Vs[row][c4 * 4 + 0] = v.x;
        Vs[row][c4 * 4 + 1] = v.y;
        Vs[row][c4 * 4 + 2] = v.z;
        Vs[row][c4 * 4 + 3] = v.w;
    }
    __syncthreads();
    #pragma unroll
    for (int it = 0; it < 4; it++) {
        int lin = it * 256 + tid;
        int hd = lin >> 4;
        int c = lin & 15;
        float4 v;
        v.x = Vs[c * 4 + 0][hd];
        v.y = Vs[c * 4 + 1][hd];
        v.z = Vs[c * 4 + 2][hd];
        v.w = Vs[c * 4 + 3][hd];
        uint2 H, L;
        split4h(v, H, L);
        size_t vi = (((size_t)bh * HDIM + hd) * SQ + s0 + c * 4) >> 2;
        Vth[vi] = H; Vtl[vi] = L;
    }
}

// ---------------------------------------------------------------------------
// Split-bf16 HMMA GEMM (NT): C = (Ah+Al)(Bh+Bl)^T, 3-pass (drop lo*lo).
// R5 re-tile: CTA 128(M) x 64(N), K-chunk 64, 2 stages (48KB each),
// 256 threads / 8 warps, warp tile 32x32 -> 2 CTAs per SM (16 warps/SM).
// Stage layout: Ah 16K | Al 16K | Bh 8K | Bl 8K; rows are 128B, SW128 swizzle.
// ---------------------------------------------------------------------------
#define G_STAGE 49152
#define GSM_TOTAL (2 * G_STAGE)

__global__ void __launch_bounds__(256, 2) gemm_mma(
    const __nv_bfloat16* __restrict__ Ah, const __nv_bfloat16* __restrict__ Al,
    const __nv_bfloat16* __restrict__ Bh, const __nv_bfloat16* __restrict__ Bl,
    float* __restrict__ C, int M, int N, int K) {
    extern __shared__ char smem[];
    const uint32_t sb = smem_to_u32(smem);
    const int tid = threadIdx.x;
    const int lane = tid & 31;
    const int wid = tid >> 5;
    const int bm = blockIdx.y * 128;
    const int bn = blockIdx.x * 64;
    const int wm = (wid >> 1) * 32;   // 4 m-warps
    const int wn = (wid & 1) * 32;    // 2 n-warps

    auto issue_stage = [&](int ch) {
        const int k0 = ch << 6;
        const uint32_t buf = sb + (uint32_t)(ch & 1) * G_STAGE;
        #pragma unroll
        for (int i = 0; i < 4; i++) {           // A: 128 rows
            int lin = tid + (i << 8);
            int row = lin >> 3;
            int c8 = lin & 7;
            uint32_t off = (uint32_t)(row << 7) + (uint32_t)(c8 << 4);
            uint32_t sw = off ^ ((off >> 3) & 0x70);
            size_t ga = (size_t)(bm + row) * K + k0 + (c8 << 3);
            cp16(buf + sw,         Ah + ga);
            cp16(buf + 16384 + sw, Al + ga);
        }
        #pragma unroll
        for (int i = 0; i < 2; i++) {           // B: 64 rows
            int lin = tid + (i << 8);
            int row = lin >> 3;
            int c8 = lin & 7;
            uint32_t off = (uint32_t)(row << 7) + (uint32_t)(c8 << 4);
            uint32_t sw = off ^ ((off >> 3) & 0x70);
            size_t gb = (size_t)(bn + row) * K + k0 + (c8 << 3);
            cp16(buf + 32768 + sw, Bh + gb);
            cp16(buf + 40960 + sw, Bl + gb);
        }
    };

    const uint32_t xorv   = (uint32_t)(lane & 7) << 4;
    const uint32_t aRowOff = (uint32_t)((wm + (lane & 15)) << 7);
    const uint32_t kaoff  = (uint32_t)((lane >> 4) << 4);
    const uint32_t bRowOff =
        (uint32_t)((wn + (lane & 7) + (((lane >> 4) & 1) << 3)) << 7);
    const uint32_t kboff  = (uint32_t)(((lane >> 3) & 1) << 4);

    float acc[2][4][4] = {};

    const int KCHUNKS = K >> 6;
    issue_stage(0); CP_COMMIT();

    for (int ch = 0; ch < KCHUNKS; ch++) {
        CP_WAIT(0);
        __syncthreads();
        if (ch + 1 < KCHUNKS) issue_stage(ch + 1);
        CP_COMMIT();

        const uint32_t buf = sb + (uint32_t)(ch & 1) * G_STAGE;
        const uint32_t aHi = buf + aRowOff;
        const uint32_t aLo = aHi + 16384;
        const uint32_t bHi = buf + 32768 + bRowOff;
        const uint32_t bLo = bHi + 8192;

        #pragma unroll
        for (int s = 0; s < 4; s++) {
            const uint32_t ca = ((uint32_t)(s << 5) + kaoff) ^ xorv;
            const uint32_t cb = ((uint32_t)(s << 5) + kboff) ^ xorv;
            uint32_t ah4[2][4], al4[2][4], bh4[2][4], bl4[2][4];
            #pragma unroll
            for (int mt = 0; mt < 2; mt++) {
                ldmx4(ah4[mt], aHi + (mt << 11) + ca);
                ldmx4(al4[mt], aLo + (mt << 11) + ca);
            }
            #pragma unroll
            for (int nt2 = 0; nt2 < 2; nt2++) {
                ldmx4(bh4[nt2], bHi + (nt2 << 11) + cb);
                ldmx4(bl4[nt2], bLo + (nt2 << 11) + cb);
            }
            #pragma unroll
            for (int mt = 0; mt < 2; mt++)
                #pragma unroll
                for (int nt = 0; nt < 4; nt++) {
                    const uint32_t b0h = bh4[nt >> 1][(nt & 1) * 2];
                    const uint32_t b1h = bh4[nt >> 1][(nt & 1) * 2 + 1];
                    const uint32_t b0l = bl4[nt >> 1][(nt & 1) * 2];
                    const uint32_t b1l = bl4[nt >> 1][(nt & 1) * 2 + 1];
                    mma_bf16(acc[mt][nt], ah4[mt], b0h, b1h);
                    mma_bf16(acc[mt][nt], ah4[mt], b0l, b1l);
                    mma_bf16(acc[mt][nt], al4[mt], b0h, b1h);
                }
        }
    }

    #pragma unroll
    for (int mt = 0; mt < 2; mt++) {
        const int r0 = bm + wm + mt * 16 + (lane >> 2);
        #pragma unroll
        for (int nt = 0; nt < 4; nt++) {
            const int c = bn + wn + nt * 8 + (lane & 3) * 2;
            float2 v0 = make_float2(acc[mt][nt][0], acc[mt][nt][1]);
            float2 v1 = make_float2(acc[mt][nt][2], acc[mt][nt][3]);
            *(float2*)&C[(size_t)r0 * N + c]       = v0;
            *(float2*)&C[(size_t)(r0 + 8) * N + c] = v1;
        }
    }
}

// ---------------------------------------------------------------------------
// fp16 tensor-core flash attention.
// S = (Qh+Ql) K^T (2 passes, K plain fp16); PV = (Ph+Pl)(Vh+Vl) 3-pass.
// CTA = (b,h) x 128 q-rows; 8 warps x 16 rows; KV tiles of 64, 3 stages.
// smem: Qh 16K | Ql 16K | 3 stages x {K 8K, Vth 8K, Vtl 8K}  (= 104KB)
// ---------------------------------------------------------------------------
#define A_STAGE 24576
#define ATT_SMEM (32768 + 3 * A_STAGE)

__global__ void __launch_bounds__(256, 1) attn_mma(
    const __half* __restrict__ Qh, const __half* __restrict__ Ql,
    const __half* __restrict__ Kf,
    const __half* __restrict__ Vth, const __half* __restrict__ Vtl,
    __nv_bfloat16* __restrict__ Oh, __nv_bfloat16* __restrict__ Ol) {
    extern __shared__ char smem[];
    const uint32_t sb = smem_to_u32(smem);
    const int tid = threadIdx.x;
    const int lane = tid & 31;
    const int wid = tid >> 5;
    const int bh = blockIdx.y;
    const int q0 = blockIdx.x * 128;

    const size_t qbase = ((size_t)bh * SQ + q0) * HDIM;
    const size_t kbase = (size_t)bh * SQ * HDIM;
    const size_t vbase = (size_t)bh * HDIM * SQ;

    const uint32_t sQh = sb;
    const uint32_t sQl = sb + 16384;

    auto issue_q = [&]() {
        #pragma unroll
        for (int i = 0; i < 4; i++) {
            int lin = tid + (i << 8);
            int row = lin >> 3;
            int c8 = lin & 7;
            uint32_t off = (uint32_t)(row << 7) + (uint32_t)(c8 << 4);
            uint32_t sw = off ^ ((off >> 3) & 0x70);
            size_t g = qbase + (size_t)row * HDIM + (c8 << 3);
            cp16(sQh + sw, Qh + g);
            cp16(sQl + sw, Ql + g);
        }
    };
    auto issue_kv = [&](int t) {
        const int kv0 = t << 6;
        const uint32_t stg = sb + 32768 + (uint32_t)(t % 3) * A_STAGE;
        #pragma unroll
        for (int i = 0; i < 2; i++) {
            int lin = tid + (i << 8);
            int row = lin >> 3;
            int c8 = lin & 7;
            uint32_t off = (uint32_t)(row << 7) + (uint32_t)(c8 << 4);
            uint32_t sw = off ^ ((off >> 3) & 0x70);
            size_t gk = kbase + (size_t)(kv0 + row) * HDIM + (c8 << 3);
            size_t gv = vbase + (size_t)row * SQ + kv0 + (c8 << 3);
            cp16(stg + sw,         Kf + gk);
            cp16(stg + 8192 + sw,  Vth + gv);
            cp16(stg + 16384 + sw, Vtl + gv);
        }
    };

    const uint32_t xorv = (uint32_t)(lane & 7) << 4;
    const uint32_t qRowOff = (uint32_t)(((wid << 4) + (lane & 15)) << 7);
    const uint32_t kaoff = (uint32_t)((lane >> 4) << 4);
    const uint32_t bRowOff =
        (uint32_t)(((lane & 7) + (((lane >> 4) & 1) << 3)) << 7);
    const uint32_t kboff = (uint32_t)(((lane >> 3) & 1) << 4);

    issue_q(); issue_kv(0); CP_COMMIT();
    issue_kv(1); CP_COMMIT();
    CP_WAIT(1);
    __syncthreads();

    // Q fragments once (warp's 16 rows x K=64)
    uint32_t qh[4][4], ql[4][4];
    #pragma unroll
    for (int kk = 0; kk < 4; kk++) {
        const uint32_t ca = ((uint32_t)(kk << 5) + kaoff) ^ xorv;
        ldmx4(qh[kk], sQh + qRowOff + ca);
        ldmx4(ql[kk], sQl + qRowOff + ca);
    }

    float m0 = -1e30f, m1 = -1e30f, l0 = 0.0f, l1 = 0.0f;
    float acc_o[8][4] = {};

    for (int t = 0; t < SQ / 64; t++) {
        CP_WAIT(1);
        __syncthreads();
        if (t + 2 < SQ / 64) issue_kv(t + 2);
        CP_COMMIT();

        const uint32_t stg = sb + 32768 + (uint32_t)(t % 3) * A_STAGE;

        // ---- S = Q K^T (2 passes: Qh*K + Ql*K) ----
        float acc_s[8][4] = {};
        #pragma unroll
        for (int kk = 0; kk < 4; kk++) {
            const uint32_t cb = ((uint32_t)(kk << 5) + kboff) ^ xorv;
            uint32_t kh4[4][4];
            #pragma unroll
            for (int nt2 = 0; nt2 < 4; nt2++)
                ldmx4(kh4[nt2], stg + bRowOff + (nt2 << 11) + cb);
            #pragma unroll
            for (int nt = 0; nt < 8; nt++) {
                const uint32_t b0 = kh4[nt >> 1][(nt & 1) * 2];
                const uint32_t b1 = kh4[nt >> 1][(nt & 1) * 2 + 1];
                mma_f16(acc_s[nt], qh[kk], b0, b1);
                mma_f16(acc_s[nt], ql[kk], b0, b1);
            }
        }

        // ---- online softmax (log2 domain) ----
        float mx0 = -1e30f, mx1 = -1e30f;
        #pragma unroll
        for (int nt = 0; nt < 8; nt++) {
            mx0 = fmaxf(mx0, fmaxf(acc_s[nt][0], acc_s[nt][1]));
            mx1 = fmaxf(mx1, fmaxf(acc_s[nt][2], acc_s[nt][3]));
        }
        mx0 = fmaxf(mx0, __shfl_xor_sync(0xffffffffu, mx0, 1));
        mx0 = fmaxf(mx0, __shfl_xor_sync(0xffffffffu, mx0, 2));
        mx1 = fmaxf(mx1, __shfl_xor_sync(0xffffffffu, mx1, 1));
        mx1 = fmaxf(mx1, __shfl_xor_sync(0xffffffffu, mx1, 2));
        const float mn0 = fmaxf(m0, mx0);
        const float mn1 = fmaxf(m1, mx1);
        const float a0 = ex2f(m0 - mn0);
        const float a1 = ex2f(m1 - mn1);
        m0 = mn0; m1 = mn1;
        float rs0 = 0.0f, rs1 = 0.0f;
        #pragma unroll
        for (int nt = 0; nt < 8; nt++) {
            acc_s[nt][0] = ex2f(acc_s[nt][0] - mn0);
            acc_s[nt][1] = ex2f(acc_s[nt][1] - mn0);
            acc_s[nt][2] = ex2f(acc_s[nt][2] - mn1);
            acc_s[nt][3] = ex2f(acc_s[nt][3] - mn1);
            rs0 += acc_s[nt][0] + acc_s[nt][1];
            rs1 += acc_s[nt][2] + acc_s[nt][3];
        }
        l0 = l0 * a0 + rs0;
        l1 = l1 * a1 + rs1;
        #pragma unroll
        for (int nt = 0; nt < 8; nt++) {
            acc_o[nt][0] *= a0; acc_o[nt][1] *= a0;
            acc_o[nt][2] *= a1; acc_o[nt][3] *= a1;
        }

        // ---- pack P into fp16 A-fragments hi/lo ----
        uint32_t phi[4][4], plo[4][4];
        #pragma unroll
        for (int kk = 0; kk < 4; kk++) {
            #pragma unroll
            for (int half = 0; half < 2; half++) {
                const float* e = acc_s[2 * kk + half];
                __half2 h01 = __floats2half2_rn(e[0], e[1]);
                __half2 h23 = __floats2half2_rn(e[2], e[3]);
                float2 f01 = __half22float2(h01);
                float2 f23 = __half22float2(h23);
                __half2 l01 = __floats2half2_rn(e[0] - f01.x, e[1] - f01.y);
                __half2 l23 = __floats2half2_rn(e[2] - f23.x, e[3] - f23.y);
                phi[kk][2 * half]     = *(uint32_t*)&h01;
                phi[kk][2 * half + 1] = *(uint32_t*)&h23;
                plo[kk][2 * half]     = *(uint32_t*)&l01;
                plo[kk][2 * half + 1] = *(uint32_t*)&l23;
            }
        }

        // ---- O += P V (3 passes: Ph*Vh + Ph*Vl + Pl*Vh) ----
        #pragma unroll
        for (int kk = 0; kk < 4; kk++) {
            const uint32_t cb = ((uint32_t)(kk << 5) + kboff) ^ xorv;
            uint32_t vh4[4][4], vl4[4][4];
            #pragma unroll
            for (int nt2 = 0; nt2 < 4; nt2++) {
                ldmx4(vh4[nt2], stg + 8192 + bRowOff + (nt2 << 11) + cb);
                ldmx4(vl4[nt2], stg + 16384 + bRowOff + (nt2 << 11) + cb);
            }
            #pragma unroll
            for (int nt = 0; nt < 8; nt++) {
                const uint32_t b0h = vh4[nt >> 1][(nt & 1) * 2];
                const uint32_t b1h = vh4[nt >> 1][(nt & 1) * 2 + 1];
                const uint32_t b0l = vl4[nt >> 1][(nt & 1) * 2];
                const uint32_t b1l = vl4[nt >> 1][(nt & 1) * 2 + 1];
                mma_f16(acc_o[nt], phi[kk], b0h, b1h);
                mma_f16(acc_o[nt], phi[kk], b0l, b1l);
                mma_f16(acc_o[nt], plo[kk], b0h, b1h);
            }
        }
    }

    // ---- epilogue: normalize, bf16 split, store [b,s,1024] ----
    l0 += __shfl_xor_sync(0xffffffffu, l0, 1);
    l0 += __shfl_xor_sync(0xffffffffu, l0, 2);
    l1 += __shfl_xor_sync(0xffffffffu, l1, 1);
    l1 += __shfl_xor_sync(0xffffffffu, l1, 2);
    const float inv0 = 1.0f / l0;
    const float inv1 = 1.0f / l1;
    const int b = bh >> 4, h = bh & 15;
    const int srow = q0 + wid * 16 + (lane >> 2);
    const size_t ob0 = ((size_t)(b * SQ + srow)) * DH + h * HDIM + 2 * (lane & 3);
    const size_t ob1 = ob0 + 8 * DH;
    #pragma unroll
    for (int nt = 0; nt < 8; nt++) {
        float o0 = acc_o[nt][0] * inv0;
        float o1 = acc_o[nt][1] * inv0;
        float o2 = acc_o[nt][2] * inv1;
        float o3 = acc_o[nt][3] * inv1;
        uint32_t u0 = __float_as_uint(o0), u1 = __float_as_uint(o1);
        uint32_t u2 = __float_as_uint(o2), u3 = __float_as_uint(o3);
        *(uint32_t*)(Oh + ob0 + nt * 8) = prmt_hi2(u0, u1);
        *(uint32_t*)(Ol + ob0 + nt * 8) = packbf2(
            o1 - __uint_as_float(u1 & 0xFFFF0000u),
            o0 - __uint_as_float(u0 & 0xFFFF0000u));
        *(uint32_t*)(Oh + ob1 + nt * 8) = prmt_hi2(u2, u3);
        *(uint32_t*)(Ol + ob1 + nt * 8) = packbf2(
            o3 - __uint_as_float(u3 & 0xFFFF0000u),
            o2 - __uint_as_float(u2 & 0xFFFF0000u));
    }
}

// ---------------------------------------------------------------------------
extern "C" void kernel_launch(void* const* d_in, const int* in_sizes, int n_in,
                              void* d_out, int out_size) {
    const float* x     = (const float*)d_in[0];
    const float* w_qkv = (const float*)d_in[1];
    const float* w_out = (const float*)d_in[2];
    float* out = (float*)d_out;

    float* qkv;
    __nv_bfloat16 *xh, *xl, *wqh, *wql, *woh, *wol, *ah, *al;
    __half *Qh, *Ql, *Kf, *Vth, *Vtl;
    cudaGetSymbolAddress((void**)&qkv, g_qkv);
    cudaGetSymbolAddress((void**)&xh, g_xh);
    cudaGetSymbolAddress((void**)&xl, g_xl);
    cudaGetSymbolAddress((void**)&wqh, g_wqh);
    cudaGetSymbolAddress((void**)&wql, g_wql);
    cudaGetSymbolAddress((void**)&woh, g_woh);
    cudaGetSymbolAddress((void**)&wol, g_wol);
    cudaGetSymbolAddress((void**)&ah, g_ah);
    cudaGetSymbolAddress((void**)&al, g_al);
    cudaGetSymbolAddress((void**)&Qh, g_Qh);
    cudaGetSymbolAddress((void**)&Ql, g_Ql);
    cudaGetSymbolAddress((void**)&Kf, g_Kf);
    cudaGetSymbolAddress((void**)&Vth, g_Vth);
    cudaGetSymbolAddress((void**)&Vtl, g_Vtl);

    cudaFuncSetAttribute(gemm_mma, cudaFuncAttributeMaxDynamicSharedMemorySize,
                         GSM_TOTAL);
    cudaFuncSetAttribute(attn_mma, cudaFuncAttributeMaxDynamicSharedMemorySize,
                         ATT_SMEM);

    const int M = BZ * SQ;                 // 4096
    const int nX  = M * DH / 4;
    const int nWq = 3 * DH * DH / 4;
    const int nWo = DH * DH / 4;

    split_hl<<<(nX + 255) / 256, 256>>>((const float4*)x, (uint2*)xh, (uint2*)xl, nX);
    split_hl<<<(nWq + 255) / 256, 256>>>((const float4*)w_qkv, (uint2*)wqh, (uint2*)wql, nWq);
    split_hl<<<(nWo + 255) / 256, 256>>>((const float4*)w_out, (uint2*)woh, (uint2*)wol, nWo);

    // 1) QKV projection -> qkv fp32
    gemm_mma<<<dim3(3 * DH / 64, M / 128), 256, GSM_TOTAL>>>(xh, xl, wqh, wql,
                                                             qkv, M, 3 * DH, DH);

    // 2) prep: head-major fp16 Q(split),K,V^T(split)
    prep_qkv<<<dim3(SQ / 64, BZ * NH), 256>>>(qkv,
        (uint2*)Qh, (uint2*)Ql, (uint2*)Kf, (uint2*)Vth, (uint2*)Vtl);

    // 3) attention -> bf16 hi/lo [b,s,1024]
    attn_mma<<<dim3(SQ / 128, BZ * NH), 256, ATT_SMEM>>>(Qh, Ql, Kf, Vth, Vtl,
                                                         ah, al);

    // 4) output projection -> d_out (fp32)
    gemm_mma<<<dim3(DH / 64, M / 128), 256, GSM_TOTAL>>>(ah, al, woh, wol, out,
                                                         M, DH, DH);
}

// round 6
// speedup vs baseline: 1.4106x; 1.4106x over previous
#include <cuda_runtime.h>
#include <cuda_bf16.h>
#include <cuda_fp16.h>
#include <cstdint>

// Problem constants
#define BZ 2
#define SQ 2048
#define DH 1024
#define NH 16
#define HDIM 64

// 0.125 * log2(e): folded into Q so softmax runs in the exp2 domain
#define SCALE_LOG2 0.18033688011112042f

// ---------------------------------------------------------------------------
// Scratch (no cudaMalloc allowed)
// ---------------------------------------------------------------------------
__device__ __align__(16) float g_qkv[(size_t)BZ * SQ * 3 * DH];   // [2,2048,3072]
__device__ __align__(16) __nv_bfloat16 g_xh[(size_t)BZ * SQ * DH];
__device__ __align__(16) __nv_bfloat16 g_xl[(size_t)BZ * SQ * DH];
__device__ __align__(16) __nv_bfloat16 g_wqh[(size_t)3 * DH * DH];
__device__ __align__(16) __nv_bfloat16 g_wql[(size_t)3 * DH * DH];
__device__ __align__(16) __nv_bfloat16 g_woh[(size_t)DH * DH];
__device__ __align__(16) __nv_bfloat16 g_wol[(size_t)DH * DH];
// head-major attention operands (fp16)
__device__ __align__(16) __half g_Qh[(size_t)BZ * NH * SQ * HDIM];
__device__ __align__(16) __half g_Ql[(size_t)BZ * NH * SQ * HDIM];
__device__ __align__(16) __half g_Kf[(size_t)BZ * NH * SQ * HDIM];
__device__ __align__(16) __half g_Vth[(size_t)BZ * NH * HDIM * SQ];
__device__ __align__(16) __half g_Vtl[(size_t)BZ * NH * HDIM * SQ];
// attention output (bf16 split, [b,s,1024])
__device__ __align__(16) __nv_bfloat16 g_ah[(size_t)BZ * SQ * DH];
__device__ __align__(16) __nv_bfloat16 g_al[(size_t)BZ * SQ * DH];

// ---------------------------------------------------------------------------
// Portable PTX helpers (sm_80+ subset; no arch-"a" features)
// ---------------------------------------------------------------------------
__device__ __forceinline__ uint32_t smem_to_u32(const void* p) {
    uint32_t a;
    asm("{ .reg .u64 t; cvta.to.shared.u64 t, %1; cvt.u32.u64 %0, t; }"
        : "=r"(a) : "l"(p));
    return a;
}

__device__ __forceinline__ void cp16(uint32_t saddr, const void* gaddr) {
    asm volatile("cp.async.cg.shared.global [%0], [%1], 16;"
                 :: "r"(saddr), "l"(gaddr));
}
#define CP_COMMIT() asm volatile("cp.async.commit_group;" ::: "memory")
#define CP_WAIT(n)  asm volatile("cp.async.wait_group %0;" :: "n"(n) : "memory")

__device__ __forceinline__ void ldmx4(uint32_t* r, uint32_t addr) {
    asm volatile("ldmatrix.sync.aligned.m8n8.x4.shared.b16 {%0,%1,%2,%3}, [%4];"
                 : "=r"(r[0]), "=r"(r[1]), "=r"(r[2]), "=r"(r[3]) : "r"(addr));
}

__device__ __forceinline__ void mma_bf16(float* d, const uint32_t* a,
                                         uint32_t b0, uint32_t b1) {
    asm volatile(
        "mma.sync.aligned.m16n8k16.row.col.f32.bf16.bf16.f32 "
        "{%0,%1,%2,%3}, {%4,%5,%6,%7}, {%8,%9}, {%0,%1,%2,%3};"
        : "+f"(d[0]), "+f"(d[1]), "+f"(d[2]), "+f"(d[3])
        : "r"(a[0]), "r"(a[1]), "r"(a[2]), "r"(a[3]), "r"(b0), "r"(b1));
}

__device__ __forceinline__ void mma_f16(float* d, const uint32_t* a,
                                        uint32_t b0, uint32_t b1) {
    asm volatile(
        "mma.sync.aligned.m16n8k16.row.col.f32.f16.f16.f32 "
        "{%0,%1,%2,%3}, {%4,%5,%6,%7}, {%8,%9}, {%0,%1,%2,%3};"
        : "+f"(d[0]), "+f"(d[1]), "+f"(d[2]), "+f"(d[3])
        : "r"(a[0]), "r"(a[1]), "r"(a[2]), "r"(a[3]), "r"(b0), "r"(b1));
}

__device__ __forceinline__ float ex2f(float x) {
    float r;
    asm("ex2.approx.f32 %0, %1;" : "=f"(r) : "f"(x));
    return r;
}
// {lo16 = hi-bf16 of a, hi16 = hi-bf16 of b}  (truncation split)
__device__ __forceinline__ uint32_t prmt_hi2(uint32_t a, uint32_t b) {
    uint32_t d;
    asm("prmt.b32 %0, %1, %2, 0x7632;" : "=r"(d) : "r"(a), "r"(b));
    return d;
}
// pack {lo16 = bf16(lo_elem), hi16 = bf16(hi_elem)} round-to-nearest
__device__ __forceinline__ uint32_t packbf2(float hi_elem, float lo_elem) {
    uint32_t d;
    asm("cvt.rn.bf16x2.f32 %0, %1, %2;" : "=r"(d) : "f"(hi_elem), "f"(lo_elem));
    return d;
}

__device__ __forceinline__ void split4(float4 v, uint2& hi, uint2& lo) {
    union { __nv_bfloat16 b[4]; uint2 u; } H, L;
    float f[4] = {v.x, v.y, v.z, v.w};
    #pragma unroll
    for (int j = 0; j < 4; j++) {
        __nv_bfloat16 h = __float2bfloat16(f[j]);
        H.b[j] = h;
        L.b[j] = __float2bfloat16(f[j] - __bfloat162float(h));
    }
    hi = H.u; lo = L.u;
}

__device__ __forceinline__ void split4h(float4 v, uint2& hi, uint2& lo) {
    union { __half b[4]; uint2 u; } H, L;
    float f[4] = {v.x, v.y, v.z, v.w};
    #pragma unroll
    for (int j = 0; j < 4; j++) {
        __half h = __float2half_rn(f[j]);
        H.b[j] = h;
        L.b[j] = __float2half_rn(f[j] - __half2float(h));
    }
    hi = H.u; lo = L.u;
}

__device__ __forceinline__ uint2 pack4h(float4 v) {
    union { __half b[4]; uint2 u; } H;
    H.b[0] = __float2half_rn(v.x);
    H.b[1] = __float2half_rn(v.y);
    H.b[2] = __float2half_rn(v.z);
    H.b[3] = __float2half_rn(v.w);
    return H.u;
}

// ---------------------------------------------------------------------------
// fp32 -> bf16 hi/lo split (4 elems/thread)
// ---------------------------------------------------------------------------
__global__ void split_hl(const float4* __restrict__ x,
                         uint2* __restrict__ hi, uint2* __restrict__ lo, int n4) {
    int i = blockIdx.x * blockDim.x + threadIdx.x;
    if (i >= n4) return;
    uint2 H, L;
    split4(x[i], H, L);
    hi[i] = H; lo[i] = L;
}

// ---------------------------------------------------------------------------
// prep_qkv: qkv fp32 [b,s,3072] -> head-major fp16:
//   Q*(0.125*log2e) split hi/lo -> [bh,s,64]; K plain -> [bh,s,64];
//   V^T split hi/lo -> [bh,64,s]
// ---------------------------------------------------------------------------
__global__ void prep_qkv(const float* __restrict__ qkv,
                         uint2* __restrict__ Qh, uint2* __restrict__ Ql,
                         uint2* __restrict__ Kf,
                         uint2* __restrict__ Vth, uint2* __restrict__ Vtl) {
    __shared__ float Vs[64][65];
    const int bh = blockIdx.y;
    const int b = bh >> 4, h = bh & 15;
    const int s0 = blockIdx.x * 64;
    const int tid = threadIdx.x;

    #pragma unroll
    for (int it = 0; it < 4; it++) {
        int lin = it * 256 + tid;
        int row = lin >> 4;     // 0..63
        int c4 = lin & 15;
        const float* base = qkv + ((size_t)(b * SQ + s0 + row)) * (3 * DH)
                                + h * HDIM + c4 * 4;
        float4 q = *(const float4*)base;
        float4 k = *(const float4*)(base + DH);
        float4 v = *(const float4*)(base + 2 * DH);
        q.x *= SCALE_LOG2; q.y *= SCALE_LOG2; q.z *= SCALE_LOG2; q.w *= SCALE_LOG2;
        uint2 H, L;
        size_t qi = (((size_t)bh * SQ + s0 + row) * HDIM + c4 * 4) >> 2;
        split4h(q, H, L); Qh[qi] = H; Ql[qi] = L;
        Kf[qi] = pack4h(k);
        Vs[row][c4 * 4 + 0] = v.x;
        Vs[row][c4 * 4 + 1] = v.y;
        Vs[row][c4 * 4 + 2] = v.z;
        Vs[row][c4 * 4 + 3] = v.w;
    }
    __syncthreads();
    #pragma unroll
    for (int it = 0; it < 4; it++) {
        int lin = it * 256 + tid;
        int hd = lin >> 4;
        int c = lin & 15;
        float4 v;
        v.x = Vs[c * 4 + 0][hd];
        v.y = Vs[c * 4 + 1][hd];
        v.z = Vs[c * 4 + 2][hd];
        v.w = Vs[c * 4 + 3][hd];
        uint2 H, L;
        split4h(v, H, L);
        size_t vi = (((size_t)bh * HDIM + hd) * SQ + s0 + c * 4) >> 2;
        Vth[vi] = H; Vtl[vi] = L;
    }
}

// ---------------------------------------------------------------------------
// Split-bf16 HMMA GEMM (NT): C = (Ah+Al)(Bh+Bl)^T, 3-pass (drop lo*lo).
// R6: same 128x128 CTA tile / K-chunk 64 / 3-stage pipeline as R4 (proven),
// but 512 threads: warps 4(m) x 4(n), warp tile 32x32 -> 2x warps for latency.
// Stage layout (64KB): Ah 16K | Al 16K | Bh 16K | Bl 16K; SW128 swizzle.
// ---------------------------------------------------------------------------
#define NSTAGE 3
#define STAGE_BYTES 65536
#define GSM_TOTAL (NSTAGE * STAGE_BYTES)

__global__ void __launch_bounds__(512, 1) gemm_mma(
    const __nv_bfloat16* __restrict__ Ah, const __nv_bfloat16* __restrict__ Al,
    const __nv_bfloat16* __restrict__ Bh, const __nv_bfloat16* __restrict__ Bl,
    float* __restrict__ C, int M, int N, int K) {
    extern __shared__ char smem[];
    const uint32_t sb = smem_to_u32(smem);
    const int tid = threadIdx.x;
    const int lane = tid & 31;
    const int wid = tid >> 5;
    const int bm = blockIdx.y * 128;
    const int bn = blockIdx.x * 128;
    const int wm = (wid >> 2) * 32;   // 4 m-warps
    const int wn = (wid & 3) * 32;    // 4 n-warps

    auto issue_stage = [&](int ch) {
        const int k0 = ch << 6;
        const uint32_t buf = sb + (uint32_t)(ch % NSTAGE) * STAGE_BYTES;
        #pragma unroll
        for (int i = 0; i < 2; i++) {     // 1024 slots / 512 threads
            int lin = tid + (i << 9);
            int row = lin >> 3;
            int c8 = lin & 7;
            uint32_t off = (uint32_t)(row << 7) + (uint32_t)(c8 << 4);
            uint32_t sw = off ^ ((off >> 3) & 0x70);
            size_t ga = (size_t)(bm + row) * K + k0 + (c8 << 3);
            size_t gb = (size_t)(bn + row) * K + k0 + (c8 << 3);
            cp16(buf + sw,         Ah + ga);
            cp16(buf + 16384 + sw, Al + ga);
            cp16(buf + 32768 + sw, Bh + gb);
            cp16(buf + 49152 + sw, Bl + gb);
        }
    };

    const uint32_t xorv   = (uint32_t)(lane & 7) << 4;
    const uint32_t aRowOff = (uint32_t)((wm + (lane & 15)) << 7);
    const uint32_t kaoff  = (uint32_t)((lane >> 4) << 4);
    const uint32_t bRowOff =
        (uint32_t)((wn + (lane & 7) + (((lane >> 4) & 1) << 3)) << 7);
    const uint32_t kboff  = (uint32_t)(((lane >> 3) & 1) << 4);

    float acc[2][4][4] = {};

    const int KCHUNKS = K >> 6;
    issue_stage(0); CP_COMMIT();
    issue_stage(1); CP_COMMIT();

    for (int ch = 0; ch < KCHUNKS; ch++) {
        CP_WAIT(1);
        __syncthreads();
        if (ch + 2 < KCHUNKS) issue_stage(ch + 2);
        CP_COMMIT();

        const uint32_t buf = sb + (uint32_t)(ch % NSTAGE) * STAGE_BYTES;
        const uint32_t aHi = buf + aRowOff;
        const uint32_t aLo = aHi + 16384;
        const uint32_t bHi = buf + 32768 + bRowOff;
        const uint32_t bLo = bHi + 16384;

        #pragma unroll
        for (int s = 0; s < 4; s++) {
            const uint32_t ca = ((uint32_t)(s << 5) + kaoff) ^ xorv;
            const uint32_t cb = ((uint32_t)(s << 5) + kboff) ^ xorv;
            uint32_t ah4[2][4], al4[2][4], bh4[2][4], bl4[2][4];
            #pragma unroll
            for (int mt = 0; mt < 2; mt++) {
                ldmx4(ah4[mt], aHi + (mt << 11) + ca);
                ldmx4(al4[mt], aLo + (mt << 11) + ca);
            }
            #pragma unroll
            for (int nt2 = 0; nt2 < 2; nt2++) {
                ldmx4(bh4[nt2], bHi + (nt2 << 11) + cb);
                ldmx4(bl4[nt2], bLo + (nt2 << 11) + cb);
            }
            #pragma unroll
            for (int mt = 0; mt < 2; mt++)
                #pragma unroll
                for (int nt = 0; nt < 4; nt++) {
                    const uint32_t b0h = bh4[nt >> 1][(nt & 1) * 2];
                    const uint32_t b1h = bh4[nt >> 1][(nt & 1) * 2 + 1];
                    const uint32_t b0l = bl4[nt >> 1][(nt & 1) * 2];
                    const uint32_t b1l = bl4[nt >> 1][(nt & 1) * 2 + 1];
                    mma_bf16(acc[mt][nt], ah4[mt], b0h, b1h);
                    mma_bf16(acc[mt][nt], ah4[mt], b0l, b1l);
                    mma_bf16(acc[mt][nt], al4[mt], b0h, b1h);
                }
        }
    }
    CP_WAIT(0);

    #pragma unroll
    for (int mt = 0; mt < 2; mt++) {
        const int r0 = bm + wm + mt * 16 + (lane >> 2);
        #pragma unroll
        for (int nt = 0; nt < 4; nt++) {
            const int c = bn + wn + nt * 8 + (lane & 3) * 2;
            float2 v0 = make_float2(acc[mt][nt][0], acc[mt][nt][1]);
            float2 v1 = make_float2(acc[mt][nt][2], acc[mt][nt][3]);
            *(float2*)&C[(size_t)r0 * N + c]       = v0;
            *(float2*)&C[(size_t)(r0 + 8) * N + c] = v1;
        }
    }
}

// ---------------------------------------------------------------------------
// fp16 tensor-core flash attention — R4 loop/sync structure (proven),
// fp16 numerics: S = (Qh+Ql) K^T (2 passes), PV = (Ph+Pl)(Vh+Vl) (3 passes).
// CTA = (b,h) x 128 q-rows; 8 warps x 16 rows; KV tiles of 64, double-buffer.
// smem: Qh 16K | Ql 16K | 2 stages x {K 8K, Vth 8K, Vtl 8K} = 80KB
// ---------------------------------------------------------------------------
#define A_STAGE 24576
#define ATT_SMEM (32768 + 2 * A_STAGE)

__global__ void __launch_bounds__(256, 1) attn_mma(
    const __half* __restrict__ Qh, const __half* __restrict__ Ql,
    const __half* __restrict__ Kf,
    const __half* __restrict__ Vth, const __half* __restrict__ Vtl,
    __nv_bfloat16* __restrict__ Oh, __nv_bfloat16* __restrict__ Ol) {
    extern __shared__ char smem[];
    const uint32_t sb = smem_to_u32(smem);
    const int tid = threadIdx.x;
    const int lane = tid & 31;
    const int wid = tid >> 5;
    const int bh = blockIdx.y;
    const int q0 = blockIdx.x * 128;

    const size_t qbase = ((size_t)bh * SQ + q0) * HDIM;
    const size_t kbase = (size_t)bh * SQ * HDIM;
    const size_t vbase = (size_t)bh * HDIM * SQ;

    const uint32_t sQh = sb;
    const uint32_t sQl = sb + 16384;

    auto issue_q = [&]() {
        #pragma unroll
        for (int i = 0; i < 4; i++) {
            int lin = tid + (i << 8);
            int row = lin >> 3;
            int c8 = lin & 7;
            uint32_t off = (uint32_t)(row << 7) + (uint32_t)(c8 << 4);
            uint32_t sw = off ^ ((off >> 3) & 0x70);
            size_t g = qbase + (size_t)row * HDIM + (c8 << 3);
            cp16(sQh + sw, Qh + g);
            cp16(sQl + sw, Ql + g);
        }
    };
    auto issue_kv = [&](int t) {
        const int kv0 = t << 6;
        const uint32_t stg = sb + 32768 + (uint32_t)(t & 1) * A_STAGE;
        #pragma unroll
        for (int i = 0; i < 2; i++) {
            int lin = tid + (i << 8);
            int row = lin >> 3;
            int c8 = lin & 7;
            uint32_t off = (uint32_t)(row << 7) + (uint32_t)(c8 << 4);
            uint32_t sw = off ^ ((off >> 3) & 0x70);
            size_t gk = kbase + (size_t)(kv0 + row) * HDIM + (c8 << 3);
            size_t gv = vbase + (size_t)row * SQ + kv0 + (c8 << 3);
            cp16(stg + sw,         Kf + gk);
            cp16(stg + 8192 + sw,  Vth + gv);
            cp16(stg + 16384 + sw, Vtl + gv);
        }
    };

    const uint32_t xorv = (uint32_t)(lane & 7) << 4;
    const uint32_t qRowOff = (uint32_t)(((wid << 4) + (lane & 15)) << 7);
    const uint32_t kaoff = (uint32_t)((lane >> 4) << 4);
    const uint32_t bRowOff =
        (uint32_t)(((lane & 7) + (((lane >> 4) & 1) << 3)) << 7);
    const uint32_t kboff = (uint32_t)(((lane >> 3) & 1) << 4);

    issue_q(); issue_kv(0); CP_COMMIT();
    issue_kv(1); CP_COMMIT();
    CP_WAIT(1);
    __syncthreads();

    // Q fragments once (warp's 16 rows x K=64)
    uint32_t qh[4][4], ql[4][4];
    #pragma unroll
    for (int kk = 0; kk < 4; kk++) {
        const uint32_t ca = ((uint32_t)(kk << 5) + kaoff) ^ xorv;
        ldmx4(qh[kk], sQh + qRowOff + ca);
        ldmx4(ql[kk], sQl + qRowOff + ca);
    }

    float m0 = -1e30f, m1 = -1e30f, l0 = 0.0f, l1 = 0.0f;
    float acc_o[8][4] = {};

    for (int t = 0; t < SQ / 64; t++) {
        const uint32_t stg = sb + 32768 + (uint32_t)(t & 1) * A_STAGE;

        // ---- S = Q K^T (2 passes: Qh*K + Ql*K) ----
        float acc_s[8][4] = {};
        #pragma unroll
        for (int kk = 0; kk < 4; kk++) {
            const uint32_t cb = ((uint32_t)(kk << 5) + kboff) ^ xorv;
            uint32_t kh4[4][4];
            #pragma unroll
            for (int nt2 = 0; nt2 < 4; nt2++)
                ldmx4(kh4[nt2], stg + bRowOff + (nt2 << 11) + cb);
            #pragma unroll
            for (int nt = 0; nt < 8; nt++) {
                const uint32_t b0 = kh4[nt >> 1][(nt & 1) * 2];
                const uint32_t b1 = kh4[nt >> 1][(nt & 1) * 2 + 1];
                mma_f16(acc_s[nt], qh[kk], b0, b1);
                mma_f16(acc_s[nt], ql[kk], b0, b1);
            }
        }

        // ---- online softmax (log2 domain) ----
        float mx0 = -1e30f, mx1 = -1e30f;
        #pragma unroll
        for (int nt = 0; nt < 8; nt++) {
            mx0 = fmaxf(mx0, fmaxf(acc_s[nt][0], acc_s[nt][1]));
            mx1 = fmaxf(mx1, fmaxf(acc_s[nt][2], acc_s[nt][3]));
        }
        mx0 = fmaxf(mx0, __shfl_xor_sync(0xffffffffu, mx0, 1));
        mx0 = fmaxf(mx0, __shfl_xor_sync(0xffffffffu, mx0, 2));
        mx1 = fmaxf(mx1, __shfl_xor_sync(0xffffffffu, mx1, 1));
        mx1 = fmaxf(mx1, __shfl_xor_sync(0xffffffffu, mx1, 2));
        const float mn0 = fmaxf(m0, mx0);
        const float mn1 = fmaxf(m1, mx1);
        const float a0 = ex2f(m0 - mn0);
        const float a1 = ex2f(m1 - mn1);
        m0 = mn0; m1 = mn1;
        float rs0 = 0.0f, rs1 = 0.0f;
        #pragma unroll
        for (int nt = 0; nt < 8; nt++) {
            acc_s[nt][0] = ex2f(acc_s[nt][0] - mn0);
            acc_s[nt][1] = ex2f(acc_s[nt][1] - mn0);
            acc_s[nt][2] = ex2f(acc_s[nt][2] - mn1);
            acc_s[nt][3] = ex2f(acc_s[nt][3] - mn1);
            rs0 += acc_s[nt][0] + acc_s[nt][1];
            rs1 += acc_s[nt][2] + acc_s[nt][3];
        }
        l0 = l0 * a0 + rs0;
        l1 = l1 * a1 + rs1;
        #pragma unroll
        for (int nt = 0; nt < 8; nt++) {
            acc_o[nt][0] *= a0; acc_o[nt][1] *= a0;
            acc_o[nt][2] *= a1; acc_o[nt][3] *= a1;
        }

        // ---- pack P into fp16 A-fragments hi/lo ----
        uint32_t phi[4][4], plo[4][4];
        #pragma unroll
        for (int kk = 0; kk < 4; kk++) {
            #pragma unroll
            for (int half = 0; half < 2; half++) {
                const float* e = acc_s[2 * kk + half];
                __half2 h01 = __floats2half2_rn(e[0], e[1]);
                __half2 h23 = __floats2half2_rn(e[2], e[3]);
                float2 f01 = __half22float2(h01);
                float2 f23 = __half22float2(h23);
                __half2 l01 = __floats2half2_rn(e[0] - f01.x, e[1] - f01.y);
                __half2 l23 = __floats2half2_rn(e[2] - f23.x, e[3] - f23.y);
                phi[kk][2 * half]     = *(uint32_t*)&h01;
                phi[kk][2 * half + 1] = *(uint32_t*)&h23;
                plo[kk][2 * half]     = *(uint32_t*)&l01;
                plo[kk][2 * half + 1] = *(uint32_t*)&l23;
            }
        }

        // ---- O += P V (3 passes: Ph*Vh + Ph*Vl + Pl*Vh) ----
        #pragma unroll
        for (int kk = 0; kk < 4; kk++) {
            const uint32_t cb = ((uint32_t)(kk << 5) + kboff) ^ xorv;
            uint32_t vh4[4][4], vl4[4][4];
            #pragma unroll
            for (int nt2 = 0; nt2 < 4; nt2++) {
                ldmx4(vh4[nt2], stg + 8192 + bRowOff + (nt2 << 11) + cb);
                ldmx4(vl4[nt2], stg + 16384 + bRowOff + (nt2 << 11) + cb);
            }
            #pragma unroll
            for (int nt = 0; nt < 8; nt++) {
                const uint32_t b0h = vh4[nt >> 1][(nt & 1) * 2];
                const uint32_t b1h = vh4[nt >> 1][(nt & 1) * 2 + 1];
                const uint32_t b0l = vl4[nt >> 1][(nt & 1) * 2];
                const uint32_t b1l = vl4[nt >> 1][(nt & 1) * 2 + 1];
                mma_f16(acc_o[nt], phi[kk], b0h, b1h);
                mma_f16(acc_o[nt], phi[kk], b0l, b1l);
                mma_f16(acc_o[nt], plo[kk], b0h, b1h);
            }
        }

        __syncthreads();
        if (t + 2 < SQ / 64) issue_kv(t + 2);
        CP_COMMIT();
        CP_WAIT(1);
        __syncthreads();
    }

    // ---- epilogue: normalize, bf16 split, store [b,s,1024] ----
    l0 += __shfl_xor_sync(0xffffffffu, l0, 1);
    l0 += __shfl_xor_sync(0xffffffffu, l0, 2);
    l1 += __shfl_xor_sync(0xffffffffu, l1, 1);
    l1 += __shfl_xor_sync(0xffffffffu, l1, 2);
    const float inv0 = 1.0f / l0;
    const float inv1 = 1.0f / l1;
    const int b = bh >> 4, h = bh & 15;
    const int srow = q0 + wid * 16 + (lane >> 2);
    const size_t ob0 = ((size_t)(b * SQ + srow)) * DH + h * HDIM + 2 * (lane & 3);
    const size_t ob1 = ob0 + 8 * DH;
    #pragma unroll
    for (int nt = 0; nt < 8; nt++) {
        float o0 = acc_o[nt][0] * inv0;
        float o1 = acc_o[nt][1] * inv0;
        float o2 = acc_o[nt][2] * inv1;
        float o3 = acc_o[nt][3] * inv1;
        uint32_t u0 = __float_as_uint(o0), u1 = __float_as_uint(o1);
        uint32_t u2 = __float_as_uint(o2), u3 = __float_as_uint(o3);
        *(uint32_t*)(Oh + ob0 + nt * 8) = prmt_hi2(u0, u1);
        *(uint32_t*)(Ol + ob0 + nt * 8) = packbf2(
            o1 - __uint_as_float(u1 & 0xFFFF0000u),
            o0 - __uint_as_float(u0 & 0xFFFF0000u));
        *(uint32_t*)(Oh + ob1 + nt * 8) = prmt_hi2(u2, u3);
        *(uint32_t*)(Ol + ob1 + nt * 8) = packbf2(
            o3 - __uint_as_float(u3 & 0xFFFF0000u),
            o2 - __uint_as_float(u2 & 0xFFFF0000u));
    }
}

// ---------------------------------------------------------------------------
extern "C" void kernel_launch(void* const* d_in, const int* in_sizes, int n_in,
                              void* d_out, int out_size) {
    const float* x     = (const float*)d_in[0];
    const float* w_qkv = (const float*)d_in[1];
    const float* w_out = (const float*)d_in[2];
    float* out = (float*)d_out;

    float* qkv;
    __nv_bfloat16 *xh, *xl, *wqh, *wql, *woh, *wol, *ah, *al;
    __half *Qh, *Ql, *Kf, *Vth, *Vtl;
    cudaGetSymbolAddress((void**)&qkv, g_qkv);
    cudaGetSymbolAddress((void**)&xh, g_xh);
    cudaGetSymbolAddress((void**)&xl, g_xl);
    cudaGetSymbolAddress((void**)&wqh, g_wqh);
    cudaGetSymbolAddress((void**)&wql, g_wql);
    cudaGetSymbolAddress((void**)&woh, g_woh);
    cudaGetSymbolAddress((void**)&wol, g_wol);
    cudaGetSymbolAddress((void**)&ah, g_ah);
    cudaGetSymbolAddress((void**)&al, g_al);
    cudaGetSymbolAddress((void**)&Qh, g_Qh);
    cudaGetSymbolAddress((void**)&Ql, g_Ql);
    cudaGetSymbolAddress((void**)&Kf, g_Kf);
    cudaGetSymbolAddress((void**)&Vth, g_Vth);
    cudaGetSymbolAddress((void**)&Vtl, g_Vtl);

    cudaFuncSetAttribute(gemm_mma, cudaFuncAttributeMaxDynamicSharedMemorySize,
                         GSM_TOTAL);
    cudaFuncSetAttribute(attn_mma, cudaFuncAttributeMaxDynamicSharedMemorySize,
                         ATT_SMEM);

    const int M = BZ * SQ;                 // 4096
    const int nX  = M * DH / 4;
    const int nWq = 3 * DH * DH / 4;
    const int nWo = DH * DH / 4;

    split_hl<<<(nX + 255) / 256, 256>>>((const float4*)x, (uint2*)xh, (uint2*)xl, nX);
    split_hl<<<(nWq + 255) / 256, 256>>>((const float4*)w_qkv, (uint2*)wqh, (uint2*)wql, nWq);
    split_hl<<<(nWo + 255) / 256, 256>>>((const float4*)w_out, (uint2*)woh, (uint2*)wol, nWo);

    // 1) QKV projection -> qkv fp32
    gemm_mma<<<dim3(3 * DH / 128, M / 128), 512, GSM_TOTAL>>>(xh, xl, wqh, wql,
                                                              qkv, M, 3 * DH, DH);

    // 2) prep: head-major fp16 Q(split),K,V^T(split)
    prep_qkv<<<dim3(SQ / 64, BZ * NH), 256>>>(qkv,
        (uint2*)Qh, (uint2*)Ql, (uint2*)Kf, (uint2*)Vth, (uint2*)Vtl);

    // 3) attention -> bf16 hi/lo [b,s,1024]
    attn_mma<<<dim3(SQ / 128, BZ * NH), 256, ATT_SMEM>>>(Qh, Ql, Kf, Vth, Vtl,
                                                         ah, al);

    // 4) output projection -> d_out (fp32)
    gemm_mma<<<dim3(DH / 128, M / 128), 512, GSM_TOTAL>>>(ah, al, woh, wol, out,
                                                          M, DH, DH);
}

// round 7
// speedup vs baseline: 1.8156x; 1.2871x over previous
#include <cuda_runtime.h>
#include <cuda_bf16.h>
#include <cuda_fp16.h>
#include <cstdint>

// Problem constants
#define BZ 2
#define SQ 2048
#define DH 1024
#define NH 16
#define HDIM 64

// 0.125 * log2(e): folded into Q so softmax runs in the exp2 domain
#define SCALE_LOG2 0.18033688011112042f

// ---------------------------------------------------------------------------
// Scratch (no cudaMalloc allowed) — all operands fp16 now
// ---------------------------------------------------------------------------
__device__ __align__(16) float g_qkv[(size_t)BZ * SQ * 3 * DH];   // [2,2048,3072]
__device__ __align__(16) __half g_xh[(size_t)BZ * SQ * DH];
__device__ __align__(16) __half g_xl[(size_t)BZ * SQ * DH];
__device__ __align__(16) __half g_wqf[(size_t)3 * DH * DH];
__device__ __align__(16) __half g_wof[(size_t)DH * DH];
// head-major attention operands (fp16)
__device__ __align__(16) __half g_Qh[(size_t)BZ * NH * SQ * HDIM];
__device__ __align__(16) __half g_Ql[(size_t)BZ * NH * SQ * HDIM];
__device__ __align__(16) __half g_Kf[(size_t)BZ * NH * SQ * HDIM];
__device__ __align__(16) __half g_Vtf[(size_t)BZ * NH * HDIM * SQ];
// attention output (fp16 split, [b,s,1024])
__device__ __align__(16) __half g_ah[(size_t)BZ * SQ * DH];
__device__ __align__(16) __half g_al[(size_t)BZ * SQ * DH];

// ---------------------------------------------------------------------------
// Portable PTX helpers (sm_80+ subset; no arch-"a" features)
// ---------------------------------------------------------------------------
__device__ __forceinline__ uint32_t smem_to_u32(const void* p) {
    uint32_t a;
    asm("{ .reg .u64 t; cvta.to.shared.u64 t, %1; cvt.u32.u64 %0, t; }"
        : "=r"(a) : "l"(p));
    return a;
}

__device__ __forceinline__ void cp16(uint32_t saddr, const void* gaddr) {
    asm volatile("cp.async.cg.shared.global [%0], [%1], 16;"
                 :: "r"(saddr), "l"(gaddr));
}
#define CP_COMMIT() asm volatile("cp.async.commit_group;" ::: "memory")
#define CP_WAIT(n)  asm volatile("cp.async.wait_group %0;" :: "n"(n) : "memory")

__device__ __forceinline__ void ldmx4(uint32_t* r, uint32_t addr) {
    asm volatile("ldmatrix.sync.aligned.m8n8.x4.shared.b16 {%0,%1,%2,%3}, [%4];"
                 : "=r"(r[0]), "=r"(r[1]), "=r"(r[2]), "=r"(r[3]) : "r"(addr));
}

__device__ __forceinline__ void mma_f16(float* d, const uint32_t* a,
                                        uint32_t b0, uint32_t b1) {
    asm volatile(
        "mma.sync.aligned.m16n8k16.row.col.f32.f16.f16.f32 "
        "{%0,%1,%2,%3}, {%4,%5,%6,%7}, {%8,%9}, {%0,%1,%2,%3};"
        : "+f"(d[0]), "+f"(d[1]), "+f"(d[2]), "+f"(d[3])
        : "r"(a[0]), "r"(a[1]), "r"(a[2]), "r"(a[3]), "r"(b0), "r"(b1));
}

__device__ __forceinline__ float ex2f(float x) {
    float r;
    asm("ex2.approx.f32 %0, %1;" : "=f"(r) : "f"(x));
    return r;
}

__device__ __forceinline__ void split4h(float4 v, uint2& hi, uint2& lo) {
    union { __half b[4]; uint2 u; } H, L;
    float f[4] = {v.x, v.y, v.z, v.w};
    #pragma unroll
    for (int j = 0; j < 4; j++) {
        __half h = __float2half_rn(f[j]);
        H.b[j] = h;
        L.b[j] = __float2half_rn(f[j] - __half2float(h));
    }
    hi = H.u; lo = L.u;
}

__device__ __forceinline__ uint2 pack4h(float4 v) {
    union { __half b[4]; uint2 u; } H;
    H.b[0] = __float2half_rn(v.x);
    H.b[1] = __float2half_rn(v.y);
    H.b[2] = __float2half_rn(v.z);
    H.b[3] = __float2half_rn(v.w);
    return H.u;
}

// ---------------------------------------------------------------------------
// fp32 -> fp16 hi/lo split, and fp32 -> fp16 pack (4 elems/thread)
// ---------------------------------------------------------------------------
__global__ void split_hl_h(const float4* __restrict__ x,
                           uint2* __restrict__ hi, uint2* __restrict__ lo, int n4) {
    int i = blockIdx.x * blockDim.x + threadIdx.x;
    if (i >= n4) return;
    uint2 H, L;
    split4h(x[i], H, L);
    hi[i] = H; lo[i] = L;
}

__global__ void pack_h(const float4* __restrict__ x, uint2* __restrict__ o, int n4) {
    int i = blockIdx.x * blockDim.x + threadIdx.x;
    if (i >= n4) return;
    o[i] = pack4h(x[i]);
}

// ---------------------------------------------------------------------------
// prep_qkv: qkv fp32 [b,s,3072] -> head-major fp16:
//   Q*(0.125*log2e) split hi/lo -> [bh,s,64]; K plain -> [bh,s,64];
//   V^T plain -> [bh,64,s]
// ---------------------------------------------------------------------------
__global__ void prep_qkv(const float* __restrict__ qkv,
                         uint2* __restrict__ Qh, uint2* __restrict__ Ql,
                         uint2* __restrict__ Kf, uint2* __restrict__ Vtf) {
    __shared__ float Vs[64][65];
    const int bh = blockIdx.y;
    const int b = bh >> 4, h = bh & 15;
    const int s0 = blockIdx.x * 64;
    const int tid = threadIdx.x;

    #pragma unroll
    for (int it = 0; it < 4; it++) {
        int lin = it * 256 + tid;
        int row = lin >> 4;     // 0..63
        int c4 = lin & 15;
        const float* base = qkv + ((size_t)(b * SQ + s0 + row)) * (3 * DH)
                                + h * HDIM + c4 * 4;
        float4 q = *(const float4*)base;
        float4 k = *(const float4*)(base + DH);
        float4 v = *(const float4*)(base + 2 * DH);
        q.x *= SCALE_LOG2; q.y *= SCALE_LOG2; q.z *= SCALE_LOG2; q.w *= SCALE_LOG2;
        uint2 H, L;
        size_t qi = (((size_t)bh * SQ + s0 + row) * HDIM + c4 * 4) >> 2;
        split4h(q, H, L); Qh[qi] = H; Ql[qi] = L;
        Kf[qi] = pack4h(k);
        Vs[row][c4 * 4 + 0] = v.x;
        Vs[row][c4 * 4 + 1] = v.y;
        Vs[row][c4 * 4 + 2] = v.z;
        Vs[row][c4 * 4 + 3] = v.w;
    }
    __syncthreads();
    #pragma unroll
    for (int it = 0; it < 4; it++) {
        int lin = it * 256 + tid;
        int hd = lin >> 4;
        int c = lin & 15;
        float4 v;
        v.x = Vs[c * 4 + 0][hd];
        v.y = Vs[c * 4 + 1][hd];
        v.z = Vs[c * 4 + 2][hd];
        v.w = Vs[c * 4 + 3][hd];
        size_t vi = (((size_t)bh * HDIM + hd) * SQ + s0 + c * 4) >> 2;
        Vtf[vi] = pack4h(v);
    }
}

// ---------------------------------------------------------------------------
// 2-pass split-fp16 HMMA GEMM (NT): C = (Ah+Al)[M,K] * Bf[N,K]^T  (fp32 out)
// CTA 128x128, K-chunk 64, 3-stage cp.async pipeline, 512 threads,
// warps 4(m)x4(n), warp tile 32x32. Stage (48KB): Ah 16K | Al 16K | Bf 16K.
// ---------------------------------------------------------------------------
#define NSTAGE 3
#define STAGE_BYTES 49152
#define GSM_TOTAL (NSTAGE * STAGE_BYTES)

__global__ void __launch_bounds__(512, 1) gemm_mma(
    const __half* __restrict__ Ah, const __half* __restrict__ Al,
    const __half* __restrict__ Bf,
    float* __restrict__ C, int M, int N, int K) {
    extern __shared__ char smem[];
    const uint32_t sb = smem_to_u32(smem);
    const int tid = threadIdx.x;
    const int lane = tid & 31;
    const int wid = tid >> 5;
    const int bm = blockIdx.y * 128;
    const int bn = blockIdx.x * 128;
    const int wm = (wid >> 2) * 32;   // 4 m-warps
    const int wn = (wid & 3) * 32;    // 4 n-warps

    auto issue_stage = [&](int ch) {
        const int k0 = ch << 6;
        const uint32_t buf = sb + (uint32_t)(ch % NSTAGE) * STAGE_BYTES;
        #pragma unroll
        for (int i = 0; i < 2; i++) {     // 1024 chunks per array / 512 threads
            int lin = tid + (i << 9);
            int row = lin >> 3;
            int c8 = lin & 7;
            uint32_t off = (uint32_t)(row << 7) + (uint32_t)(c8 << 4);
            uint32_t sw = off ^ ((off >> 3) & 0x70);
            size_t ga = (size_t)(bm + row) * K + k0 + (c8 << 3);
            size_t gb = (size_t)(bn + row) * K + k0 + (c8 << 3);
            cp16(buf + sw,         Ah + ga);
            cp16(buf + 16384 + sw, Al + ga);
            cp16(buf + 32768 + sw, Bf + gb);
        }
    };

    const uint32_t xorv   = (uint32_t)(lane & 7) << 4;
    const uint32_t aRowOff = (uint32_t)((wm + (lane & 15)) << 7);
    const uint32_t kaoff  = (uint32_t)((lane >> 4) << 4);
    const uint32_t bRowOff =
        (uint32_t)((wn + (lane & 7) + (((lane >> 4) & 1) << 3)) << 7);
    const uint32_t kboff  = (uint32_t)(((lane >> 3) & 1) << 4);

    float acc[2][4][4] = {};

    const int KCHUNKS = K >> 6;
    issue_stage(0); CP_COMMIT();
    issue_stage(1); CP_COMMIT();

    for (int ch = 0; ch < KCHUNKS; ch++) {
        CP_WAIT(1);
        __syncthreads();
        if (ch + 2 < KCHUNKS) issue_stage(ch + 2);
        CP_COMMIT();

        const uint32_t buf = sb + (uint32_t)(ch % NSTAGE) * STAGE_BYTES;
        const uint32_t aHi = buf + aRowOff;
        const uint32_t aLo = aHi + 16384;
        const uint32_t bF  = buf + 32768 + bRowOff;

        #pragma unroll
        for (int s = 0; s < 4; s++) {
            const uint32_t ca = ((uint32_t)(s << 5) + kaoff) ^ xorv;
            const uint32_t cb = ((uint32_t)(s << 5) + kboff) ^ xorv;
            uint32_t ah4[2][4], al4[2][4], b4[2][4];
            #pragma unroll
            for (int mt = 0; mt < 2; mt++) {
                ldmx4(ah4[mt], aHi + (mt << 11) + ca);
                ldmx4(al4[mt], aLo + (mt << 11) + ca);
            }
            #pragma unroll
            for (int nt2 = 0; nt2 < 2; nt2++)
                ldmx4(b4[nt2], bF + (nt2 << 11) + cb);
            #pragma unroll
            for (int mt = 0; mt < 2; mt++)
                #pragma unroll
                for (int nt = 0; nt < 4; nt++) {
                    const uint32_t b0 = b4[nt >> 1][(nt & 1) * 2];
                    const uint32_t b1 = b4[nt >> 1][(nt & 1) * 2 + 1];
                    mma_f16(acc[mt][nt], ah4[mt], b0, b1);
                    mma_f16(acc[mt][nt], al4[mt], b0, b1);
                }
        }
    }
    CP_WAIT(0);

    #pragma unroll
    for (int mt = 0; mt < 2; mt++) {
        const int r0 = bm + wm + mt * 16 + (lane >> 2);
        #pragma unroll
        for (int nt = 0; nt < 4; nt++) {
            const int c = bn + wn + nt * 8 + (lane & 3) * 2;
            float2 v0 = make_float2(acc[mt][nt][0], acc[mt][nt][1]);
            float2 v1 = make_float2(acc[mt][nt][2], acc[mt][nt][3]);
            *(float2*)&C[(size_t)r0 * N + c]       = v0;
            *(float2*)&C[(size_t)(r0 + 8) * N + c] = v1;
        }
    }
}

// ---------------------------------------------------------------------------
// fp16 tensor-core flash attention (R4/R6 structure).
// S = (Qh+Ql) K^T (2 passes); PV = (Ph+Pl) V (2 passes, V plain fp16).
// CTA = (b,h) x 128 q-rows; 8 warps x 16 rows; KV tiles of 64, double-buffer.
// smem: Qh 16K | Ql 16K | 2 stages x {K 8K, Vtf 8K} = 64KB
// Output: fp16 hi/lo [b,s,1024], feeding the out-proj GEMM.
// ---------------------------------------------------------------------------
#define A_STAGE 16384
#define ATT_SMEM (32768 + 2 * A_STAGE)

__global__ void __launch_bounds__(256, 1) attn_mma(
    const __half* __restrict__ Qh, const __half* __restrict__ Ql,
    const __half* __restrict__ Kf, const __half* __restrict__ Vtf,
    __half* __restrict__ Oh, __half* __restrict__ Ol) {
    extern __shared__ char smem[];
    const uint32_t sb = smem_to_u32(smem);
    const int tid = threadIdx.x;
    const int lane = tid & 31;
    const int wid = tid >> 5;
    const int bh = blockIdx.y;
    const int q0 = blockIdx.x * 128;

    const size_t qbase = ((size_t)bh * SQ + q0) * HDIM;
    const size_t kbase = (size_t)bh * SQ * HDIM;
    const size_t vbase = (size_t)bh * HDIM * SQ;

    const uint32_t sQh = sb;
    const uint32_t sQl = sb + 16384;

    auto issue_q = [&]() {
        #pragma unroll
        for (int i = 0; i < 4; i++) {
            int lin = tid + (i << 8);
            int row = lin >> 3;
            int c8 = lin & 7;
            uint32_t off = (uint32_t)(row << 7) + (uint32_t)(c8 << 4);
            uint32_t sw = off ^ ((off >> 3) & 0x70);
            size_t g = qbase + (size_t)row * HDIM + (c8 << 3);
            cp16(sQh + sw, Qh + g);
            cp16(sQl + sw, Ql + g);
        }
    };
    auto issue_kv = [&](int t) {
        const int kv0 = t << 6;
        const uint32_t stg = sb + 32768 + (uint32_t)(t & 1) * A_STAGE;
        #pragma unroll
        for (int i = 0; i < 2; i++) {
            int lin = tid + (i << 8);
            int row = lin >> 3;
            int c8 = lin & 7;
            uint32_t off = (uint32_t)(row << 7) + (uint32_t)(c8 << 4);
            uint32_t sw = off ^ ((off >> 3) & 0x70);
            size_t gk = kbase + (size_t)(kv0 + row) * HDIM + (c8 << 3);
            size_t gv = vbase + (size_t)row * SQ + kv0 + (c8 << 3);
            cp16(stg + sw,        Kf + gk);
            cp16(stg + 8192 + sw, Vtf + gv);
        }
    };

    const uint32_t xorv = (uint32_t)(lane & 7) << 4;
    const uint32_t qRowOff = (uint32_t)(((wid << 4) + (lane & 15)) << 7);
    const uint32_t kaoff = (uint32_t)((lane >> 4) << 4);
    const uint32_t bRowOff =
        (uint32_t)(((lane & 7) + (((lane >> 4) & 1) << 3)) << 7);
    const uint32_t kboff = (uint32_t)(((lane >> 3) & 1) << 4);

    issue_q(); issue_kv(0); CP_COMMIT();
    issue_kv(1); CP_COMMIT();
    CP_WAIT(1);
    __syncthreads();

    // Q fragments once (warp's 16 rows x K=64)
    uint32_t qh[4][4], ql[4][4];
    #pragma unroll
    for (int kk = 0; kk < 4; kk++) {
        const uint32_t ca = ((uint32_t)(kk << 5) + kaoff) ^ xorv;
        ldmx4(qh[kk], sQh + qRowOff + ca);
        ldmx4(ql[kk], sQl + qRowOff + ca);
    }

    float m0 = -1e30f, m1 = -1e30f, l0 = 0.0f, l1 = 0.0f;
    float acc_o[8][4] = {};

    for (int t = 0; t < SQ / 64; t++) {
        const uint32_t stg = sb + 32768 + (uint32_t)(t & 1) * A_STAGE;

        // ---- S = Q K^T (2 passes: Qh*K + Ql*K) ----
        float acc_s[8][4] = {};
        #pragma unroll
        for (int kk = 0; kk < 4; kk++) {
            const uint32_t cb = ((uint32_t)(kk << 5) + kboff) ^ xorv;
            uint32_t kh4[4][4];
            #pragma unroll
            for (int nt2 = 0; nt2 < 4; nt2++)
                ldmx4(kh4[nt2], stg + bRowOff + (nt2 << 11) + cb);
            #pragma unroll
            for (int nt = 0; nt < 8; nt++) {
                const uint32_t b0 = kh4[nt >> 1][(nt & 1) * 2];
                const uint32_t b1 = kh4[nt >> 1][(nt & 1) * 2 + 1];
                mma_f16(acc_s[nt], qh[kk], b0, b1);
                mma_f16(acc_s[nt], ql[kk], b0, b1);
            }
        }

        // ---- online softmax (log2 domain) ----
        float mx0 = -1e30f, mx1 = -1e30f;
        #pragma unroll
        for (int nt = 0; nt < 8; nt++) {
            mx0 = fmaxf(mx0, fmaxf(acc_s[nt][0], acc_s[nt][1]));
            mx1 = fmaxf(mx1, fmaxf(acc_s[nt][2], acc_s[nt][3]));
        }
        mx0 = fmaxf(mx0, __shfl_xor_sync(0xffffffffu, mx0, 1));
        mx0 = fmaxf(mx0, __shfl_xor_sync(0xffffffffu, mx0, 2));
        mx1 = fmaxf(mx1, __shfl_xor_sync(0xffffffffu, mx1, 1));
        mx1 = fmaxf(mx1, __shfl_xor_sync(0xffffffffu, mx1, 2));
        const float mn0 = fmaxf(m0, mx0);
        const float mn1 = fmaxf(m1, mx1);
        const float a0 = ex2f(m0 - mn0);
        const float a1 = ex2f(m1 - mn1);
        m0 = mn0; m1 = mn1;
        float rs0 = 0.0f, rs1 = 0.0f;
        #pragma unroll
        for (int nt = 0; nt < 8; nt++) {
            acc_s[nt][0] = ex2f(acc_s[nt][0] - mn0);
            acc_s[nt][1] = ex2f(acc_s[nt][1] - mn0);
            acc_s[nt][2] = ex2f(acc_s[nt][2] - mn1);
            acc_s[nt][3] = ex2f(acc_s[nt][3] - mn1);
            rs0 += acc_s[nt][0] + acc_s[nt][1];
            rs1 += acc_s[nt][2] + acc_s[nt][3];
        }
        l0 = l0 * a0 + rs0;
        l1 = l1 * a1 + rs1;
        #pragma unroll
        for (int nt = 0; nt < 8; nt++) {
            acc_o[nt][0] *= a0; acc_o[nt][1] *= a0;
            acc_o[nt][2] *= a1; acc_o[nt][3] *= a1;
        }

        // ---- pack P into fp16 A-fragments hi/lo ----
        uint32_t phi[4][4], plo[4][4];
        #pragma unroll
        for (int kk = 0; kk < 4; kk++) {
            #pragma unroll
            for (int half = 0; half < 2; half++) {
                const float* e = acc_s[2 * kk + half];
                __half2 h01 = __floats2half2_rn(e[0], e[1]);
                __half2 h23 = __floats2half2_rn(e[2], e[3]);
                float2 f01 = __half22float2(h01);
                float2 f23 = __half22float2(h23);
                __half2 l01 = __floats2half2_rn(e[0] - f01.x, e[1] - f01.y);
                __half2 l23 = __floats2half2_rn(e[2] - f23.x, e[3] - f23.y);
                phi[kk][2 * half]     = *(uint32_t*)&h01;
                phi[kk][2 * half + 1] = *(uint32_t*)&h23;
                plo[kk][2 * half]     = *(uint32_t*)&l01;
                plo[kk][2 * half + 1] = *(uint32_t*)&l23;
            }
        }

        // ---- O += P V (2 passes: Ph*V + Pl*V) ----
        #pragma unroll
        for (int kk = 0; kk < 4; kk++) {
            const uint32_t cb = ((uint32_t)(kk << 5) + kboff) ^ xorv;
            uint32_t vh4[4][4];
            #pragma unroll
            for (int nt2 = 0; nt2 < 4; nt2++)
                ldmx4(vh4[nt2], stg + 8192 + bRowOff + (nt2 << 11) + cb);
            #pragma unroll
            for (int nt = 0; nt < 8; nt++) {
                const uint32_t b0 = vh4[nt >> 1][(nt & 1) * 2];
                const uint32_t b1 = vh4[nt >> 1][(nt & 1) * 2 + 1];
                mma_f16(acc_o[nt], phi[kk], b0, b1);
                mma_f16(acc_o[nt], plo[kk], b0, b1);
            }
        }

        __syncthreads();
        if (t + 2 < SQ / 64) issue_kv(t + 2);
        CP_COMMIT();
        CP_WAIT(1);
        __syncthreads();
    }

    // ---- epilogue: normalize, fp16 split, store [b,s,1024] ----
    l0 += __shfl_xor_sync(0xffffffffu, l0, 1);
    l0 += __shfl_xor_sync(0xffffffffu, l0, 2);
    l1 += __shfl_xor_sync(0xffffffffu, l1, 1);
    l1 += __shfl_xor_sync(0xffffffffu, l1, 2);
    const float inv0 = 1.0f / l0;
    const float inv1 = 1.0f / l1;
    const int b = bh >> 4, h = bh & 15;
    const int srow = q0 + wid * 16 + (lane >> 2);
    const size_t ob0 = ((size_t)(b * SQ + srow)) * DH + h * HDIM + 2 * (lane & 3);
    const size_t ob1 = ob0 + 8 * DH;
    #pragma unroll
    for (int nt = 0; nt < 8; nt++) {
        float o0 = acc_o[nt][0] * inv0;
        float o1 = acc_o[nt][1] * inv0;
        float o2 = acc_o[nt][2] * inv1;
        float o3 = acc_o[nt][3] * inv1;
        __half2 h01 = __floats2half2_rn(o0, o1);
        __half2 h23 = __floats2half2_rn(o2, o3);
        float2 f01 = __half22float2(h01);
        float2 f23 = __half22float2(h23);
        __half2 l01 = __floats2half2_rn(o0 - f01.x, o1 - f01.y);
        __half2 l23 = __floats2half2_rn(o2 - f23.x, o3 - f23.y);
        *(uint32_t*)(Oh + ob0 + nt * 8) = *(uint32_t*)&h01;
        *(uint32_t*)(Ol + ob0 + nt * 8) = *(uint32_t*)&l01;
        *(uint32_t*)(Oh + ob1 + nt * 8) = *(uint32_t*)&h23;
        *(uint32_t*)(Ol + ob1 + nt * 8) = *(uint32_t*)&l23;
    }
}

// ---------------------------------------------------------------------------
extern "C" void kernel_launch(void* const* d_in, const int* in_sizes, int n_in,
                              void* d_out, int out_size) {
    const float* x     = (const float*)d_in[0];
    const float* w_qkv = (const float*)d_in[1];
    const float* w_out = (const float*)d_in[2];
    float* out = (float*)d_out;

    float* qkv;
    __half *xh, *xl, *wqf, *wof, *ah, *al;
    __half *Qh, *Ql, *Kf, *Vtf;
    cudaGetSymbolAddress((void**)&qkv, g_qkv);
    cudaGetSymbolAddress((void**)&xh, g_xh);
    cudaGetSymbolAddress((void**)&xl, g_xl);
    cudaGetSymbolAddress((void**)&wqf, g_wqf);
    cudaGetSymbolAddress((void**)&wof, g_wof);
    cudaGetSymbolAddress((void**)&ah, g_ah);
    cudaGetSymbolAddress((void**)&al, g_al);
    cudaGetSymbolAddress((void**)&Qh, g_Qh);
    cudaGetSymbolAddress((void**)&Ql, g_Ql);
    cudaGetSymbolAddress((void**)&Kf, g_Kf);
    cudaGetSymbolAddress((void**)&Vtf, g_Vtf);

    cudaFuncSetAttribute(gemm_mma, cudaFuncAttributeMaxDynamicSharedMemorySize,
                         GSM_TOTAL);
    cudaFuncSetAttribute(attn_mma, cudaFuncAttributeMaxDynamicSharedMemorySize,
                         ATT_SMEM);

    const int M = BZ * SQ;                 // 4096
    const int nX  = M * DH / 4;
    const int nWq = 3 * DH * DH / 4;
    const int nWo = DH * DH / 4;

    split_hl_h<<<(nX + 255) / 256, 256>>>((const float4*)x, (uint2*)xh, (uint2*)xl, nX);
    pack_h<<<(nWq + 255) / 256, 256>>>((const float4*)w_qkv, (uint2*)wqf, nWq);
    pack_h<<<(nWo + 255) / 256, 256>>>((const float4*)w_out, (uint2*)wof, nWo);

    // 1) QKV projection -> qkv fp32
    gemm_mma<<<dim3(3 * DH / 128, M / 128), 512, GSM_TOTAL>>>(xh, xl, wqf,
                                                              qkv, M, 3 * DH, DH);

    // 2) prep: head-major fp16 Q(split), K, V^T
    prep_qkv<<<dim3(SQ / 64, BZ * NH), 256>>>(qkv,
        (uint2*)Qh, (uint2*)Ql, (uint2*)Kf, (uint2*)Vtf);

    // 3) attention -> fp16 hi/lo [b,s,1024]
    attn_mma<<<dim3(SQ / 128, BZ * NH), 256, ATT_SMEM>>>(Qh, Ql, Kf, Vtf,
                                                         ah, al);

    // 4) output projection -> d_out (fp32)
    gemm_mma<<<dim3(DH / 128, M / 128), 512, GSM_TOTAL>>>(ah, al, wof, out,
                                                          M, DH, DH);
}

// round 8
// speedup vs baseline: 2.1026x; 1.1581x over previous
#include <cuda_runtime.h>
#include <cuda_bf16.h>
#include <cuda_fp16.h>
#include <cstdint>

// Problem constants
#define BZ 2
#define SQ 2048
#define DH 1024
#define NH 16
#define HDIM 64

// 0.125 * log2(e): folded into Q so softmax runs in the exp2 domain
#define SCALE_LOG2 0.18033688011112042f

// ---------------------------------------------------------------------------
// Scratch (no cudaMalloc allowed)
// ---------------------------------------------------------------------------
__device__ __align__(16) float g_qkv[(size_t)BZ * SQ * 3 * DH];   // [2,2048,3072]
__device__ __align__(16) __half g_xh[(size_t)BZ * SQ * DH];
__device__ __align__(16) __half g_xl[(size_t)BZ * SQ * DH];
__device__ __align__(16) __half g_wqf[(size_t)3 * DH * DH];
__device__ __align__(16) __half g_wof[(size_t)DH * DH];
// head-major attention operands (fp16)
__device__ __align__(16) __half g_Qh[(size_t)BZ * NH * SQ * HDIM];
__device__ __align__(16) __half g_Ql[(size_t)BZ * NH * SQ * HDIM];
__device__ __align__(16) __half g_Kf[(size_t)BZ * NH * SQ * HDIM];
__device__ __align__(16) __half g_Vtf[(size_t)BZ * NH * HDIM * SQ];
// attention output (fp16 split, [b,s,1024])
__device__ __align__(16) __half g_ah[(size_t)BZ * SQ * DH];
__device__ __align__(16) __half g_al[(size_t)BZ * SQ * DH];

// ---------------------------------------------------------------------------
// Portable PTX helpers (sm_80+ subset; no arch-"a" features)
// ---------------------------------------------------------------------------
__device__ __forceinline__ uint32_t smem_to_u32(const void* p) {
    uint32_t a;
    asm("{ .reg .u64 t; cvta.to.shared.u64 t, %1; cvt.u32.u64 %0, t; }"
        : "=r"(a) : "l"(p));
    return a;
}

__device__ __forceinline__ void cp16(uint32_t saddr, const void* gaddr) {
    asm volatile("cp.async.cg.shared.global [%0], [%1], 16;"
                 :: "r"(saddr), "l"(gaddr));
}
#define CP_COMMIT() asm volatile("cp.async.commit_group;" ::: "memory")
#define CP_WAIT(n)  asm volatile("cp.async.wait_group %0;" :: "n"(n) : "memory")

__device__ __forceinline__ void ldmx4(uint32_t* r, uint32_t addr) {
    asm volatile("ldmatrix.sync.aligned.m8n8.x4.shared.b16 {%0,%1,%2,%3}, [%4];"
                 : "=r"(r[0]), "=r"(r[1]), "=r"(r[2]), "=r"(r[3]) : "r"(addr));
}

__device__ __forceinline__ void mma_f16(float* d, const uint32_t* a,
                                        uint32_t b0, uint32_t b1) {
    asm volatile(
        "mma.sync.aligned.m16n8k16.row.col.f32.f16.f16.f32 "
        "{%0,%1,%2,%3}, {%4,%5,%6,%7}, {%8,%9}, {%0,%1,%2,%3};"
        : "+f"(d[0]), "+f"(d[1]), "+f"(d[2]), "+f"(d[3])
        : "r"(a[0]), "r"(a[1]), "r"(a[2]), "r"(a[3]), "r"(b0), "r"(b1));
}

__device__ __forceinline__ float ex2f(float x) {
    float r;
    asm("ex2.approx.f32 %0, %1;" : "=f"(r) : "f"(x));
    return r;
}

__device__ __forceinline__ void split4h(float4 v, uint2& hi, uint2& lo) {
    union { __half b[4]; uint2 u; } H, L;
    float f[4] = {v.x, v.y, v.z, v.w};
    #pragma unroll
    for (int j = 0; j < 4; j++) {
        __half h = __float2half_rn(f[j]);
        H.b[j] = h;
        L.b[j] = __float2half_rn(f[j] - __half2float(h));
    }
    hi = H.u; lo = L.u;
}

__device__ __forceinline__ uint2 pack4h(float4 v) {
    union { __half b[4]; uint2 u; } H;
    H.b[0] = __float2half_rn(v.x);
    H.b[1] = __float2half_rn(v.y);
    H.b[2] = __float2half_rn(v.z);
    H.b[3] = __float2half_rn(v.w);
    return H.u;
}

// ---------------------------------------------------------------------------
// fp32 -> fp16 hi/lo split, and fp32 -> fp16 pack (4 elems/thread)
// ---------------------------------------------------------------------------
__global__ void split_hl_h(const float4* __restrict__ x,
                           uint2* __restrict__ hi, uint2* __restrict__ lo, int n4) {
    int i = blockIdx.x * blockDim.x + threadIdx.x;
    if (i >= n4) return;
    uint2 H, L;
    split4h(x[i], H, L);
    hi[i] = H; lo[i] = L;
}

__global__ void pack_h(const float4* __restrict__ x, uint2* __restrict__ o, int n4) {
    int i = blockIdx.x * blockDim.x + threadIdx.x;
    if (i >= n4) return;
    o[i] = pack4h(x[i]);
}

// ---------------------------------------------------------------------------
// prep_qkv: qkv fp32 [b,s,3072] -> head-major fp16:
//   Q*(0.125*log2e) split hi/lo -> [bh,s,64]; K plain -> [bh,s,64];
//   V^T plain -> [bh,64,s]
// ---------------------------------------------------------------------------
__global__ void prep_qkv(const float* __restrict__ qkv,
                         uint2* __restrict__ Qh, uint2* __restrict__ Ql,
                         uint2* __restrict__ Kf, uint2* __restrict__ Vtf) {
    __shared__ float Vs[64][65];
    const int bh = blockIdx.y;
    const int b = bh >> 4, h = bh & 15;
    const int s0 = blockIdx.x * 64;
    const int tid = threadIdx.x;

    #pragma unroll
    for (int it = 0; it < 4; it++) {
        int lin = it * 256 + tid;
        int row = lin >> 4;     // 0..63
        int c4 = lin & 15;
        const float* base = qkv + ((size_t)(b * SQ + s0 + row)) * (3 * DH)
                                + h * HDIM + c4 * 4;
        float4 q = *(const float4*)base;
        float4 k = *(const float4*)(base + DH);
        float4 v = *(const float4*)(base + 2 * DH);
        q.x *= SCALE_LOG2; q.y *= SCALE_LOG2; q.z *= SCALE_LOG2; q.w *= SCALE_LOG2;
        uint2 H, L;
        size_t qi = (((size_t)bh * SQ + s0 + row) * HDIM + c4 * 4) >> 2;
        split4h(q, H, L); Qh[qi] = H; Ql[qi] = L;
        Kf[qi] = pack4h(k);
        Vs[row][c4 * 4 + 0] = v.x;
        Vs[row][c4 * 4 + 1] = v.y;
        Vs[row][c4 * 4 + 2] = v.z;
        Vs[row][c4 * 4 + 3] = v.w;
    }
    __syncthreads();
    #pragma unroll
    for (int it = 0; it < 4; it++) {
        int lin = it * 256 + tid;
        int hd = lin >> 4;
        int c = lin & 15;
        float4 v;
        v.x = Vs[c * 4 + 0][hd];
        v.y = Vs[c * 4 + 1][hd];
        v.z = Vs[c * 4 + 2][hd];
        v.w = Vs[c * 4 + 3][hd];
        size_t vi = (((size_t)bh * HDIM + hd) * SQ + s0 + c * 4) >> 2;
        Vtf[vi] = pack4h(v);
    }
}

// ---------------------------------------------------------------------------
// 2-pass split-fp16 HMMA GEMM (NT): C = (Ah+Al)[M,K] * Bf[N,K]^T  (fp32 out)
// R8: CTA 128x128, K-chunk 32, 2 stages x 24KB = 48KB -> 2 CTAs/SM.
// 256 threads, warps 4(m) x 2(n), warp tile 32x64, acc 64 regs.
// Rows are 64B (32 halfs): swizzle off ^ ((off>>3)&0x30)  (Swizzle<2,4,3>).
// Stage: Ah 8K | Al 8K | Bf 8K.
// ---------------------------------------------------------------------------
#define G_STAGE 24576
#define GSM_TOTAL (2 * G_STAGE)

__global__ void __launch_bounds__(256, 2) gemm_mma(
    const __half* __restrict__ Ah, const __half* __restrict__ Al,
    const __half* __restrict__ Bf,
    float* __restrict__ C, int M, int N, int K) {
    extern __shared__ char smem[];
    const uint32_t sb = smem_to_u32(smem);
    const int tid = threadIdx.x;
    const int lane = tid & 31;
    const int wid = tid >> 5;
    const int bm = blockIdx.y * 128;
    const int bn = blockIdx.x * 128;
    const int wm = (wid >> 1) * 32;   // 4 m-warps
    const int wn = (wid & 1) * 64;    // 2 n-warps

    // loader: 3 arrays x 128 rows x 64B = 512 16B-chunks each / 256 threads
    auto issue_stage = [&](int ch) {
        const int k0 = ch << 5;
        const uint32_t buf = sb + (uint32_t)(ch & 1) * G_STAGE;
        #pragma unroll
        for (int i = 0; i < 2; i++) {
            int lin = tid + (i << 8);
            int row = lin >> 2;
            int c4 = lin & 3;
            uint32_t off = (uint32_t)(row << 6) + (uint32_t)(c4 << 4);
            uint32_t sw = off ^ ((off >> 3) & 0x30);
            size_t ga = (size_t)(bm + row) * K + k0 + (c4 << 3);
            size_t gb = (size_t)(bn + row) * K + k0 + (c4 << 3);
            cp16(buf + sw,         Ah + ga);
            cp16(buf + 8192 + sw,  Al + ga);
            cp16(buf + 16384 + sw, Bf + gb);
        }
    };

    // fragment addressing (64B rows): xor = row bits [1:2] -> addr bits [4:5]
    const uint32_t xorv   = (uint32_t)(lane & 6) << 3;
    const uint32_t aRowOff = (uint32_t)((wm + (lane & 15)) << 6);
    const uint32_t kaoff  = (uint32_t)((lane >> 4) << 4);
    const uint32_t bRowOff =
        (uint32_t)((wn + (lane & 7) + (((lane >> 4) & 1) << 3)) << 6);
    const uint32_t kboff  = (uint32_t)(((lane >> 3) & 1) << 4);

    float acc[2][8][4] = {};

    const int KCHUNKS = K >> 5;
    issue_stage(0); CP_COMMIT();

    for (int ch = 0; ch < KCHUNKS; ch++) {
        CP_WAIT(0);
        __syncthreads();
        if (ch + 1 < KCHUNKS) issue_stage(ch + 1);
        CP_COMMIT();

        const uint32_t buf = sb + (uint32_t)(ch & 1) * G_STAGE;
        const uint32_t aHi = buf + aRowOff;
        const uint32_t aLo = aHi + 8192;
        const uint32_t bF  = buf + 16384 + bRowOff;

        #pragma unroll
        for (int s = 0; s < 2; s++) {          // 2 x k16 within the chunk
            const uint32_t ca = ((uint32_t)(s << 5) + kaoff) ^ xorv;
            const uint32_t cb = ((uint32_t)(s << 5) + kboff) ^ xorv;
            uint32_t ah4[2][4], al4[2][4], b4[4][4];
            #pragma unroll
            for (int mt = 0; mt < 2; mt++) {
                ldmx4(ah4[mt], aHi + (mt << 10) + ca);
                ldmx4(al4[mt], aLo + (mt << 10) + ca);
            }
            #pragma unroll
            for (int nt2 = 0; nt2 < 4; nt2++)
                ldmx4(b4[nt2], bF + (nt2 << 10) + cb);
            #pragma unroll
            for (int mt = 0; mt < 2; mt++)
                #pragma unroll
                for (int nt = 0; nt < 8; nt++) {
                    const uint32_t b0 = b4[nt >> 1][(nt & 1) * 2];
                    const uint32_t b1 = b4[nt >> 1][(nt & 1) * 2 + 1];
                    mma_f16(acc[mt][nt], ah4[mt], b0, b1);
                    mma_f16(acc[mt][nt], al4[mt], b0, b1);
                }
        }
    }

    #pragma unroll
    for (int mt = 0; mt < 2; mt++) {
        const int r0 = bm + wm + mt * 16 + (lane >> 2);
        #pragma unroll
        for (int nt = 0; nt < 8; nt++) {
            const int c = bn + wn + nt * 8 + (lane & 3) * 2;
            float2 v0 = make_float2(acc[mt][nt][0], acc[mt][nt][1]);
            float2 v1 = make_float2(acc[mt][nt][2], acc[mt][nt][3]);
            *(float2*)&C[(size_t)r0 * N + c]       = v0;
            *(float2*)&C[(size_t)(r0 + 8) * N + c] = v1;
        }
    }
}

// ---------------------------------------------------------------------------
// fp16 tensor-core flash attention.
// S = (Qh+Ql) K^T (2 passes); PV = P V (1 pass, P = rn-fp16 of exp2 values).
// CTA = (b,h) x 128 q-rows; 8 warps x 16 rows; KV tiles of 64, double-buffer.
// smem 32KB total: prologue holds Qh|Ql (16K+16K); after Q is register-
// resident the same 32KB becomes the 2 KV stages (each: K 8K | Vtf 8K).
// Output: fp16 hi/lo [b,s,1024] feeding the out-proj GEMM.
// ---------------------------------------------------------------------------
#define A_STAGE 16384
#define ATT_SMEM 32768

__global__ void __launch_bounds__(256, 1) attn_mma(
    const __half* __restrict__ Qh, const __half* __restrict__ Ql,
    const __half* __restrict__ Kf, const __half* __restrict__ Vtf,
    __half* __restrict__ Oh, __half* __restrict__ Ol) {
    extern __shared__ char smem[];
    const uint32_t sb = smem_to_u32(smem);
    const int tid = threadIdx.x;
    const int lane = tid & 31;
    const int wid = tid >> 5;
    const int bh = blockIdx.y;
    const int q0 = blockIdx.x * 128;

    const size_t qbase = ((size_t)bh * SQ + q0) * HDIM;
    const size_t kbase = (size_t)bh * SQ * HDIM;
    const size_t vbase = (size_t)bh * HDIM * SQ;

    auto issue_q = [&]() {
        #pragma unroll
        for (int i = 0; i < 4; i++) {
            int lin = tid + (i << 8);
            int row = lin >> 3;
            int c8 = lin & 7;
            uint32_t off = (uint32_t)(row << 7) + (uint32_t)(c8 << 4);
            uint32_t sw = off ^ ((off >> 3) & 0x70);
            size_t g = qbase + (size_t)row * HDIM + (c8 << 3);
            cp16(sb + sw,         Qh + g);
            cp16(sb + 16384 + sw, Ql + g);
        }
    };
    auto issue_kv = [&](int t) {
        const int kv0 = t << 6;
        const uint32_t stg = sb + (uint32_t)(t & 1) * A_STAGE;
        #pragma unroll
        for (int i = 0; i < 2; i++) {
            int lin = tid + (i << 8);
            int row = lin >> 3;
            int c8 = lin & 7;
            uint32_t off = (uint32_t)(row << 7) + (uint32_t)(c8 << 4);
            uint32_t sw = off ^ ((off >> 3) & 0x70);
            size_t gk = kbase + (size_t)(kv0 + row) * HDIM + (c8 << 3);
            size_t gv = vbase + (size_t)row * SQ + kv0 + (c8 << 3);
            cp16(stg + sw,        Kf + gk);
            cp16(stg + 8192 + sw, Vtf + gv);
        }
    };

    const uint32_t xorv = (uint32_t)(lane & 7) << 4;
    const uint32_t qRowOff = (uint32_t)(((wid << 4) + (lane & 15)) << 7);
    const uint32_t kaoff = (uint32_t)((lane >> 4) << 4);
    const uint32_t bRowOff =
        (uint32_t)(((lane & 7) + (((lane >> 4) & 1) << 3)) << 7);
    const uint32_t kboff = (uint32_t)(((lane >> 3) & 1) << 4);

    // ---- prologue: Q -> registers, then recycle smem for KV stages ----
    issue_q(); CP_COMMIT();
    CP_WAIT(0);
    __syncthreads();

    uint32_t qh[4][4], ql[4][4];
    #pragma unroll
    for (int kk = 0; kk < 4; kk++) {
        const uint32_t ca = ((uint32_t)(kk << 5) + kaoff) ^ xorv;
        ldmx4(qh[kk], sb + qRowOff + ca);
        ldmx4(ql[kk], sb + 16384 + qRowOff + ca);
    }
    __syncthreads();            // all warps done reading Q smem

    issue_kv(0); CP_COMMIT();
    issue_kv(1); CP_COMMIT();
    CP_WAIT(1);
    __syncthreads();

    float m0 = -1e30f, m1 = -1e30f, l0 = 0.0f, l1 = 0.0f;
    float acc_o[8][4] = {};

    for (int t = 0; t < SQ / 64; t++) {
        const uint32_t stg = sb + (uint32_t)(t & 1) * A_STAGE;

        // ---- S = Q K^T (2 passes: Qh*K + Ql*K) ----
        float acc_s[8][4] = {};
        #pragma unroll
        for (int kk = 0; kk < 4; kk++) {
            const uint32_t cb = ((uint32_t)(kk << 5) + kboff) ^ xorv;
            uint32_t kh4[4][4];
            #pragma unroll
            for (int nt2 = 0; nt2 < 4; nt2++)
                ldmx4(kh4[nt2], stg + bRowOff + (nt2 << 11) + cb);
            #pragma unroll
            for (int nt = 0; nt < 8; nt++) {
                const uint32_t b0 = kh4[nt >> 1][(nt & 1) * 2];
                const uint32_t b1 = kh4[nt >> 1][(nt & 1) * 2 + 1];
                mma_f16(acc_s[nt], qh[kk], b0, b1);
                mma_f16(acc_s[nt], ql[kk], b0, b1);
            }
        }

        // ---- online softmax (log2 domain) ----
        float mx0 = -1e30f, mx1 = -1e30f;
        #pragma unroll
        for (int nt = 0; nt < 8; nt++) {
            mx0 = fmaxf(mx0, fmaxf(acc_s[nt][0], acc_s[nt][1]));
            mx1 = fmaxf(mx1, fmaxf(acc_s[nt][2], acc_s[nt][3]));
        }
        mx0 = fmaxf(mx0, __shfl_xor_sync(0xffffffffu, mx0, 1));
        mx0 = fmaxf(mx0, __shfl_xor_sync(0xffffffffu, mx0, 2));
        mx1 = fmaxf(mx1, __shfl_xor_sync(0xffffffffu, mx1, 1));
        mx1 = fmaxf(mx1, __shfl_xor_sync(0xffffffffu, mx1, 2));
        const float mn0 = fmaxf(m0, mx0);
        const float mn1 = fmaxf(m1, mx1);
        const float a0 = ex2f(m0 - mn0);
        const float a1 = ex2f(m1 - mn1);
        m0 = mn0; m1 = mn1;
        float rs0 = 0.0f, rs1 = 0.0f;
        #pragma unroll
        for (int nt = 0; nt < 8; nt++) {
            acc_s[nt][0] = ex2f(acc_s[nt][0] - mn0);
            acc_s[nt][1] = ex2f(acc_s[nt][1] - mn0);
            acc_s[nt][2] = ex2f(acc_s[nt][2] - mn1);
            acc_s[nt][3] = ex2f(acc_s[nt][3] - mn1);
            rs0 += acc_s[nt][0] + acc_s[nt][1];
            rs1 += acc_s[nt][2] + acc_s[nt][3];
        }
        l0 = l0 * a0 + rs0;
        l1 = l1 * a1 + rs1;
        #pragma unroll
        for (int nt = 0; nt < 8; nt++) {
            acc_o[nt][0] *= a0; acc_o[nt][1] *= a0;
            acc_o[nt][2] *= a1; acc_o[nt][3] *= a1;
        }

        // ---- pack P into fp16 A-fragments (single precision pass) ----
        uint32_t pfrag[4][4];
        #pragma unroll
        for (int kk = 0; kk < 4; kk++) {
            #pragma unroll
            for (int half = 0; half < 2; half++) {
                const float* e = acc_s[2 * kk + half];
                __half2 h01 = __floats2half2_rn(e[0], e[1]);
                __half2 h23 = __floats2half2_rn(e[2], e[3]);
                pfrag[kk][2 * half]     = *(uint32_t*)&h01;
                pfrag[kk][2 * half + 1] = *(uint32_t*)&h23;
            }
        }

        // ---- O += P V (1 pass) ----
        #pragma unroll
        for (int kk = 0; kk < 4; kk++) {
            const uint32_t cb = ((uint32_t)(kk << 5) + kboff) ^ xorv;
            uint32_t vh4[4][4];
            #pragma unroll
            for (int nt2 = 0; nt2 < 4; nt2++)
                ldmx4(vh4[nt2], stg + 8192 + bRowOff + (nt2 << 11) + cb);
            #pragma unroll
            for (int nt = 0; nt < 8; nt++) {
                const uint32_t b0 = vh4[nt >> 1][(nt & 1) * 2];
                const uint32_t b1 = vh4[nt >> 1][(nt & 1) * 2 + 1];
                mma_f16(acc_o[nt], pfrag[kk], b0, b1);
            }
        }

        __syncthreads();
        if (t + 2 < SQ / 64) issue_kv(t + 2);
        CP_COMMIT();
        CP_WAIT(1);
        __syncthreads();
    }

    // ---- epilogue: normalize, fp16 split, store [b,s,1024] ----
    l0 += __shfl_xor_sync(0xffffffffu, l0, 1);
    l0 += __shfl_xor_sync(0xffffffffu, l0, 2);
    l1 += __shfl_xor_sync(0xffffffffu, l1, 1);
    l1 += __shfl_xor_sync(0xffffffffu, l1, 2);
    const float inv0 = 1.0f / l0;
    const float inv1 = 1.0f / l1;
    const int b = bh >> 4, h = bh & 15;
    const int srow = q0 + wid * 16 + (lane >> 2);
    const size_t ob0 = ((size_t)(b * SQ + srow)) * DH + h * HDIM + 2 * (lane & 3);
    const size_t ob1 = ob0 + 8 * DH;
    #pragma unroll
    for (int nt = 0; nt < 8; nt++) {
        float o0 = acc_o[nt][0] * inv0;
        float o1 = acc_o[nt][1] * inv0;
        float o2 = acc_o[nt][2] * inv1;
        float o3 = acc_o[nt][3] * inv1;
        __half2 h01 = __floats2half2_rn(o0, o1);
        __half2 h23 = __floats2half2_rn(o2, o3);
        float2 f01 = __half22float2(h01);
        float2 f23 = __half22float2(h23);
        __half2 l01 = __floats2half2_rn(o0 - f01.x, o1 - f01.y);
        __half2 l23 = __floats2half2_rn(o2 - f23.x, o3 - f23.y);
        *(uint32_t*)(Oh + ob0 + nt * 8) = *(uint32_t*)&h01;
        *(uint32_t*)(Ol + ob0 + nt * 8) = *(uint32_t*)&l01;
        *(uint32_t*)(Oh + ob1 + nt * 8) = *(uint32_t*)&h23;
        *(uint32_t*)(Ol + ob1 + nt * 8) = *(uint32_t*)&l23;
    }
}

// ---------------------------------------------------------------------------
extern "C" void kernel_launch(void* const* d_in, const int* in_sizes, int n_in,
                              void* d_out, int out_size) {
    const float* x     = (const float*)d_in[0];
    const float* w_qkv = (const float*)d_in[1];
    const float* w_out = (const float*)d_in[2];
    float* out = (float*)d_out;

    float* qkv;
    __half *xh, *xl, *wqf, *wof, *ah, *al;
    __half *Qh, *Ql, *Kf, *Vtf;
    cudaGetSymbolAddress((void**)&qkv, g_qkv);
    cudaGetSymbolAddress((void**)&xh, g_xh);
    cudaGetSymbolAddress((void**)&xl, g_xl);
    cudaGetSymbolAddress((void**)&wqf, g_wqf);
    cudaGetSymbolAddress((void**)&wof, g_wof);
    cudaGetSymbolAddress((void**)&ah, g_ah);
    cudaGetSymbolAddress((void**)&al, g_al);
    cudaGetSymbolAddress((void**)&Qh, g_Qh);
    cudaGetSymbolAddress((void**)&Ql, g_Ql);
    cudaGetSymbolAddress((void**)&Kf, g_Kf);
    cudaGetSymbolAddress((void**)&Vtf, g_Vtf);

    cudaFuncSetAttribute(gemm_mma, cudaFuncAttributeMaxDynamicSharedMemorySize,
                         GSM_TOTAL);
    cudaFuncSetAttribute(attn_mma, cudaFuncAttributeMaxDynamicSharedMemorySize,
                         ATT_SMEM);

    const int M = BZ * SQ;                 // 4096
    const int nX  = M * DH / 4;
    const int nWq = 3 * DH * DH / 4;
    const int nWo = DH * DH / 4;

    split_hl_h<<<(nX + 255) / 256, 256>>>((const float4*)x, (uint2*)xh, (uint2*)xl, nX);
    pack_h<<<(nWq + 255) / 256, 256>>>((const float4*)w_qkv, (uint2*)wqf, nWq);
    pack_h<<<(nWo + 255) / 256, 256>>>((const float4*)w_out, (uint2*)wof, nWo);

    // 1) QKV projection -> qkv fp32
    gemm_mma<<<dim3(3 * DH / 128, M / 128), 256, GSM_TOTAL>>>(xh, xl, wqf,
                                                              qkv, M, 3 * DH, DH);

    // 2) prep: head-major fp16 Q(split), K, V^T
    prep_qkv<<<dim3(SQ / 64, BZ * NH), 256>>>(qkv,
        (uint2*)Qh, (uint2*)Ql, (uint2*)Kf, (uint2*)Vtf);

    // 3) attention -> fp16 hi/lo [b,s,1024]
    attn_mma<<<dim3(SQ / 128, BZ * NH), 256, ATT_SMEM>>>(Qh, Ql, Kf, Vtf,
                                                         ah, al);

    // 4) output projection -> d_out (fp32)
    gemm_mma<<<dim3(DH / 128, M / 128), 256, GSM_TOTAL>>>(ah, al, wof, out,
                                                          M, DH, DH);
}

// round 9
// speedup vs baseline: 2.1277x; 1.0119x over previous
#include <cuda_runtime.h>
#include <cuda_bf16.h>
#include <cuda_fp16.h>
#include <cstdint>

// Problem constants
#define BZ 2
#define SQ 2048
#define DH 1024
#define NH 16
#define HDIM 64

// 0.125 * log2(e): folded into Q so softmax runs in the exp2 domain
#define SCALE_LOG2 0.18033688011112042f

// ---------------------------------------------------------------------------
// Scratch (no cudaMalloc allowed)
// ---------------------------------------------------------------------------
__device__ __align__(16) __half g_xh[(size_t)BZ * SQ * DH];
__device__ __align__(16) __half g_xl[(size_t)BZ * SQ * DH];
__device__ __align__(16) __half g_wqf[(size_t)3 * DH * DH];
__device__ __align__(16) __half g_wof[(size_t)DH * DH];
// head-major attention operands (fp16)
__device__ __align__(16) __half g_Qh[(size_t)BZ * NH * SQ * HDIM];
__device__ __align__(16) __half g_Ql[(size_t)BZ * NH * SQ * HDIM];
__device__ __align__(16) __half g_Kf[(size_t)BZ * NH * SQ * HDIM];
__device__ __align__(16) __half g_Vf[(size_t)BZ * NH * SQ * HDIM];   // [bh,s,64]
__device__ __align__(16) __half g_Vtf[(size_t)BZ * NH * HDIM * SQ];  // [bh,64,s]
// attention output (fp16 split, [b,s,1024])
__device__ __align__(16) __half g_ah[(size_t)BZ * SQ * DH];
__device__ __align__(16) __half g_al[(size_t)BZ * SQ * DH];

// ---------------------------------------------------------------------------
// Portable PTX helpers (sm_80+ subset; no arch-"a" features)
// ---------------------------------------------------------------------------
__device__ __forceinline__ uint32_t smem_to_u32(const void* p) {
    uint32_t a;
    asm("{ .reg .u64 t; cvta.to.shared.u64 t, %1; cvt.u32.u64 %0, t; }"
        : "=r"(a) : "l"(p));
    return a;
}

__device__ __forceinline__ void cp16(uint32_t saddr, const void* gaddr) {
    asm volatile("cp.async.cg.shared.global [%0], [%1], 16;"
                 :: "r"(saddr), "l"(gaddr));
}
#define CP_COMMIT() asm volatile("cp.async.commit_group;" ::: "memory")
#define CP_WAIT(n)  asm volatile("cp.async.wait_group %0;" :: "n"(n) : "memory")

__device__ __forceinline__ void ldmx4(uint32_t* r, uint32_t addr) {
    asm volatile("ldmatrix.sync.aligned.m8n8.x4.shared.b16 {%0,%1,%2,%3}, [%4];"
                 : "=r"(r[0]), "=r"(r[1]), "=r"(r[2]), "=r"(r[3]) : "r"(addr));
}

__device__ __forceinline__ void mma_f16(float* d, const uint32_t* a,
                                        uint32_t b0, uint32_t b1) {
    asm volatile(
        "mma.sync.aligned.m16n8k16.row.col.f32.f16.f16.f32 "
        "{%0,%1,%2,%3}, {%4,%5,%6,%7}, {%8,%9}, {%0,%1,%2,%3};"
        : "+f"(d[0]), "+f"(d[1]), "+f"(d[2]), "+f"(d[3])
        : "r"(a[0]), "r"(a[1]), "r"(a[2]), "r"(a[3]), "r"(b0), "r"(b1));
}

__device__ __forceinline__ float ex2f(float x) {
    float r;
    asm("ex2.approx.f32 %0, %1;" : "=f"(r) : "f"(x));
    return r;
}

__device__ __forceinline__ void split4h(float4 v, uint2& hi, uint2& lo) {
    union { __half b[4]; uint2 u; } H, L;
    float f[4] = {v.x, v.y, v.z, v.w};
    #pragma unroll
    for (int j = 0; j < 4; j++) {
        __half h = __float2half_rn(f[j]);
        H.b[j] = h;
        L.b[j] = __float2half_rn(f[j] - __half2float(h));
    }
    hi = H.u; lo = L.u;
}

__device__ __forceinline__ uint2 pack4h(float4 v) {
    union { __half b[4]; uint2 u; } H;
    H.b[0] = __float2half_rn(v.x);
    H.b[1] = __float2half_rn(v.y);
    H.b[2] = __float2half_rn(v.z);
    H.b[3] = __float2half_rn(v.w);
    return H.u;
}

// ---------------------------------------------------------------------------
// prep_in: one kernel for x split + both weight packs (index-ranged)
// ---------------------------------------------------------------------------
__global__ void prep_in(const float4* __restrict__ x,
                        const float4* __restrict__ wq,
                        const float4* __restrict__ wo,
                        uint2* __restrict__ xh, uint2* __restrict__ xl,
                        uint2* __restrict__ wqf, uint2* __restrict__ wof,
                        int nX, int nWq, int nWo) {
    int i = blockIdx.x * blockDim.x + threadIdx.x;
    if (i < nX) {
        uint2 H, L;
        split4h(x[i], H, L);
        xh[i] = H; xl[i] = L;
    } else if (i < nX + nWq) {
        wqf[i - nX] = pack4h(wq[i - nX]);
    } else if (i < nX + nWq + nWo) {
        wof[i - nX - nWq] = pack4h(wo[i - nX - nWq]);
    }
}

// ---------------------------------------------------------------------------
// transp_v: V [bh,s,64] fp16 -> Vt [bh,64,s] fp16 (64x64 smem tiles)
// ---------------------------------------------------------------------------
__global__ void transp_v(const __half* __restrict__ Vf, __half* __restrict__ Vtf) {
    __shared__ __half Vs[64][72];
    const int bh = blockIdx.y;
    const int s0 = blockIdx.x * 64;
    const int tid = threadIdx.x;
    const size_t src = ((size_t)bh * SQ + s0) * HDIM;
    #pragma unroll
    for (int it = 0; it < 2; it++) {
        int lin = it * 256 + tid;
        int row = lin >> 3;
        int c8 = lin & 7;
        union { uint4 u; __half h[8]; } t;
        t.u = *(const uint4*)(Vf + src + (size_t)row * HDIM + c8 * 8);
        #pragma unroll
        for (int j = 0; j < 8; j++) Vs[row][c8 * 8 + j] = t.h[j];
    }
    __syncthreads();
    #pragma unroll
    for (int it = 0; it < 2; it++) {
        int lin = it * 256 + tid;
        int hd = lin >> 3;
        int c8 = lin & 7;
        union { uint4 u; __half h[8]; } t;
        #pragma unroll
        for (int j = 0; j < 8; j++) t.h[j] = Vs[c8 * 8 + j][hd];
        *(uint4*)(Vtf + ((size_t)bh * HDIM + hd) * SQ + s0 + c8 * 8) = t.u;
    }
}

// ---------------------------------------------------------------------------
// Shared GEMM mainloop config (R8-proven): CTA 128x128, K-chunk 32,
// 2 stages x 24KB = 48KB -> 2 CTAs/SM. 256 threads, warps 4(m) x 2(n),
// warp tile 32x64. Rows 64B; swizzle off ^ ((off>>3)&0x30).
// ---------------------------------------------------------------------------
#define G_STAGE 24576
#define GSM_TOTAL (2 * G_STAGE)

// Mainloop as a macro-free inline pattern shared by both kernels via template.
template <int FUSED_QKV>
__device__ __forceinline__ void gemm_body(
    const __half* __restrict__ Ah, const __half* __restrict__ Al,
    const __half* __restrict__ Bf,
    float* __restrict__ C,
    __half* __restrict__ Qh, __half* __restrict__ Ql,
    __half* __restrict__ Kf, __half* __restrict__ Vf,
    int M, int N, int K, char* smem) {
    const uint32_t sb = smem_to_u32(smem);
    const int tid = threadIdx.x;
    const int lane = tid & 31;
    const int wid = tid >> 5;
    const int bm = blockIdx.y * 128;
    const int bn = blockIdx.x * 128;
    const int wm = (wid >> 1) * 32;   // 4 m-warps
    const int wn = (wid & 1) * 64;    // 2 n-warps

    auto issue_stage = [&](int ch) {
        const int k0 = ch << 5;
        const uint32_t buf = sb + (uint32_t)(ch & 1) * G_STAGE;
        #pragma unroll
        for (int i = 0; i < 2; i++) {
            int lin = tid + (i << 8);
            int row = lin >> 2;
            int c4 = lin & 3;
            uint32_t off = (uint32_t)(row << 6) + (uint32_t)(c4 << 4);
            uint32_t sw = off ^ ((off >> 3) & 0x30);
            size_t ga = (size_t)(bm + row) * K + k0 + (c4 << 3);
            size_t gb = (size_t)(bn + row) * K + k0 + (c4 << 3);
            cp16(buf + sw,         Ah + ga);
            cp16(buf + 8192 + sw,  Al + ga);
            cp16(buf + 16384 + sw, Bf + gb);
        }
    };

    const uint32_t xorv   = (uint32_t)(lane & 6) << 3;
    const uint32_t aRowOff = (uint32_t)((wm + (lane & 15)) << 6);
    const uint32_t kaoff  = (uint32_t)((lane >> 4) << 4);
    const uint32_t bRowOff =
        (uint32_t)((wn + (lane & 7) + (((lane >> 4) & 1) << 3)) << 6);
    const uint32_t kboff  = (uint32_t)(((lane >> 3) & 1) << 4);

    float acc[2][8][4] = {};

    const int KCHUNKS = K >> 5;
    issue_stage(0); CP_COMMIT();

    for (int ch = 0; ch < KCHUNKS; ch++) {
        CP_WAIT(0);
        __syncthreads();
        if (ch + 1 < KCHUNKS) issue_stage(ch + 1);
        CP_COMMIT();

        const uint32_t buf = sb + (uint32_t)(ch & 1) * G_STAGE;
        const uint32_t aHi = buf + aRowOff;
        const uint32_t aLo = aHi + 8192;
        const uint32_t bF  = buf + 16384 + bRowOff;

        #pragma unroll
        for (int s = 0; s < 2; s++) {
            const uint32_t ca = ((uint32_t)(s << 5) + kaoff) ^ xorv;
            const uint32_t cb = ((uint32_t)(s << 5) + kboff) ^ xorv;
            uint32_t ah4[2][4], al4[2][4], b4[4][4];
            #pragma unroll
            for (int mt = 0; mt < 2; mt++) {
                ldmx4(ah4[mt], aHi + (mt << 10) + ca);
                ldmx4(al4[mt], aLo + (mt << 10) + ca);
            }
            #pragma unroll
            for (int nt2 = 0; nt2 < 4; nt2++)
                ldmx4(b4[nt2], bF + (nt2 << 10) + cb);
            #pragma unroll
            for (int mt = 0; mt < 2; mt++)
                #pragma unroll
                for (int nt = 0; nt < 8; nt++) {
                    const uint32_t b0 = b4[nt >> 1][(nt & 1) * 2];
                    const uint32_t b1 = b4[nt >> 1][(nt & 1) * 2 + 1];
                    mma_f16(acc[mt][nt], ah4[mt], b0, b1);
                    mma_f16(acc[mt][nt], al4[mt], b0, b1);
                }
        }
    }

    if (FUSED_QKV) {
        // region constant per CTA: 0=Q, 1=K, 2=V  (N must be 3072)
        const int region = bn >> 10;
        const int cbase = (bn & 1023) + wn;
        #pragma unroll
        for (int mt = 0; mt < 2; mt++) {
            #pragma unroll
            for (int hr = 0; hr < 2; hr++) {
                const int r = bm + wm + mt * 16 + (lane >> 2) + hr * 8;
                const int bb = r >> 11, ss = r & (SQ - 1);
                #pragma unroll
                for (int nt = 0; nt < 8; nt++) {
                    const int cc = cbase + nt * 8 + (lane & 3) * 2;
                    const int h = cc >> 6, d = cc & 63;
                    const size_t idx =
                        (((size_t)(bb * NH + h) * SQ + ss) << 6) + d;
                    float v0 = acc[mt][nt][hr * 2 + 0];
                    float v1 = acc[mt][nt][hr * 2 + 1];
                    if (region == 0) {
                        v0 *= SCALE_LOG2; v1 *= SCALE_LOG2;
                        __half2 hh = __floats2half2_rn(v0, v1);
                        float2 ff = __half22float2(hh);
                        __half2 ll = __floats2half2_rn(v0 - ff.x, v1 - ff.y);
                        *(uint32_t*)(Qh + idx) = *(uint32_t*)&hh;
                        *(uint32_t*)(Ql + idx) = *(uint32_t*)&ll;
                    } else if (region == 1) {
                        __half2 hh = __floats2half2_rn(v0, v1);
                        *(uint32_t*)(Kf + idx) = *(uint32_t*)&hh;
                    } else {
                        __half2 hh = __floats2half2_rn(v0, v1);
                        *(uint32_t*)(Vf + idx) = *(uint32_t*)&hh;
                    }
                }
            }
        }
    } else {
        #pragma unroll
        for (int mt = 0; mt < 2; mt++) {
            const int r0 = bm + wm + mt * 16 + (lane >> 2);
            #pragma unroll
            for (int nt = 0; nt < 8; nt++) {
                const int c = bn + wn + nt * 8 + (lane & 3) * 2;
                float2 v0 = make_float2(acc[mt][nt][0], acc[mt][nt][1]);
                float2 v1 = make_float2(acc[mt][nt][2], acc[mt][nt][3]);
                *(float2*)&C[(size_t)r0 * N + c]       = v0;
                *(float2*)&C[(size_t)(r0 + 8) * N + c] = v1;
            }
        }
    }
}

__global__ void __launch_bounds__(256, 2) gemm_mma(
    const __half* __restrict__ Ah, const __half* __restrict__ Al,
    const __half* __restrict__ Bf,
    float* __restrict__ C, int M, int N, int K) {
    extern __shared__ char smem[];
    gemm_body<0>(Ah, Al, Bf, C, nullptr, nullptr, nullptr, nullptr,
                 M, N, K, smem);
}

__global__ void __launch_bounds__(256, 2) gemm_qkv(
    const __half* __restrict__ Ah, const __half* __restrict__ Al,
    const __half* __restrict__ Bf,
    __half* __restrict__ Qh, __half* __restrict__ Ql,
    __half* __restrict__ Kf, __half* __restrict__ Vf,
    int M, int N, int K) {
    extern __shared__ char smem[];
    gemm_body<1>(Ah, Al, Bf, nullptr, Qh, Ql, Kf, Vf, M, N, K, smem);
}

// ---------------------------------------------------------------------------
// fp16 tensor-core flash attention (R8-proven).
// S = (Qh+Ql) K^T (2 passes); PV = P V (1 pass).
// CTA = (b,h) x 128 q-rows; 8 warps x 16 rows; KV tiles of 64, double-buffer.
// smem 32KB: prologue Qh|Ql, then recycled as 2 KV stages {K 8K | Vt 8K}.
// ---------------------------------------------------------------------------
#define A_STAGE 16384
#define ATT_SMEM 32768

__global__ void __launch_bounds__(256, 1) attn_mma(
    const __half* __restrict__ Qh, const __half* __restrict__ Ql,
    const __half* __restrict__ Kf, const __half* __restrict__ Vtf,
    __half* __restrict__ Oh, __half* __restrict__ Ol) {
    extern __shared__ char smem[];
    const uint32_t sb = smem_to_u32(smem);
    const int tid = threadIdx.x;
    const int lane = tid & 31;
    const int wid = tid >> 5;
    const int bh = blockIdx.y;
    const int q0 = blockIdx.x * 128;

    const size_t qbase = ((size_t)bh * SQ + q0) * HDIM;
    const size_t kbase = (size_t)bh * SQ * HDIM;
    const size_t vbase = (size_t)bh * HDIM * SQ;

    auto issue_q = [&]() {
        #pragma unroll
        for (int i = 0; i < 4; i++) {
            int lin = tid + (i << 8);
            int row = lin >> 3;
            int c8 = lin & 7;
            uint32_t off = (uint32_t)(row << 7) + (uint32_t)(c8 << 4);
            uint32_t sw = off ^ ((off >> 3) & 0x70);
            size_t g = qbase + (size_t)row * HDIM + (c8 << 3);
            cp16(sb + sw,         Qh + g);
            cp16(sb + 16384 + sw, Ql + g);
        }
    };
    auto issue_kv = [&](int t) {
        const int kv0 = t << 6;
        const uint32_t stg = sb + (uint32_t)(t & 1) * A_STAGE;
        #pragma unroll
        for (int i = 0; i < 2; i++) {
            int lin = tid + (i << 8);
            int row = lin >> 3;
            int c8 = lin & 7;
            uint32_t off = (uint32_t)(row << 7) + (uint32_t)(c8 << 4);
            uint32_t sw = off ^ ((off >> 3) & 0x70);
            size_t gk = kbase + (size_t)(kv0 + row) * HDIM + (c8 << 3);
            size_t gv = vbase + (size_t)row * SQ + kv0 + (c8 << 3);
            cp16(stg + sw,        Kf + gk);
            cp16(stg + 8192 + sw, Vtf + gv);
        }
    };

    const uint32_t xorv = (uint32_t)(lane & 7) << 4;
    const uint32_t qRowOff = (uint32_t)(((wid << 4) + (lane & 15)) << 7);
    const uint32_t kaoff = (uint32_t)((lane >> 4) << 4);
    const uint32_t bRowOff =
        (uint32_t)(((lane & 7) + (((lane >> 4) & 1) << 3)) << 7);
    const uint32_t kboff = (uint32_t)(((lane >> 3) & 1) << 4);

    // ---- prologue: Q -> registers, then recycle smem for KV stages ----
    issue_q(); CP_COMMIT();
    CP_WAIT(0);
    __syncthreads();

    uint32_t qh[4][4], ql[4][4];
    #pragma unroll
    for (int kk = 0; kk < 4; kk++) {
        const uint32_t ca = ((uint32_t)(kk << 5) + kaoff) ^ xorv;
        ldmx4(qh[kk], sb + qRowOff + ca);
        ldmx4(ql[kk], sb + 16384 + qRowOff + ca);
    }
    __syncthreads();

    issue_kv(0); CP_COMMIT();
    issue_kv(1); CP_COMMIT();
    CP_WAIT(1);
    __syncthreads();

    float m0 = -1e30f, m1 = -1e30f, l0 = 0.0f, l1 = 0.0f;
    float acc_o[8][4] = {};

    for (int t = 0; t < SQ / 64; t++) {
        const uint32_t stg = sb + (uint32_t)(t & 1) * A_STAGE;

        // ---- S = Q K^T (2 passes: Qh*K + Ql*K) ----
        float acc_s[8][4] = {};
        #pragma unroll
        for (int kk = 0; kk < 4; kk++) {
            const uint32_t cb = ((uint32_t)(kk << 5) + kboff) ^ xorv;
            uint32_t kh4[4][4];
            #pragma unroll
            for (int nt2 = 0; nt2 < 4; nt2++)
                ldmx4(kh4[nt2], stg + bRowOff + (nt2 << 11) + cb);
            #pragma unroll
            for (int nt = 0; nt < 8; nt++) {
                const uint32_t b0 = kh4[nt >> 1][(nt & 1) * 2];
                const uint32_t b1 = kh4[nt >> 1][(nt & 1) * 2 + 1];
                mma_f16(acc_s[nt], qh[kk], b0, b1);
                mma_f16(acc_s[nt], ql[kk], b0, b1);
            }
        }

        // ---- online softmax (log2 domain) ----
        float mx0 = -1e30f, mx1 = -1e30f;
        #pragma unroll
        for (int nt = 0; nt < 8; nt++) {
            mx0 = fmaxf(mx0, fmaxf(acc_s[nt][0], acc_s[nt][1]));
            mx1 = fmaxf(mx1, fmaxf(acc_s[nt][2], acc_s[nt][3]));
        }
        mx0 = fmaxf(mx0, __shfl_xor_sync(0xffffffffu, mx0, 1));
        mx0 = fmaxf(mx0, __shfl_xor_sync(0xffffffffu, mx0, 2));
        mx1 = fmaxf(mx1, __shfl_xor_sync(0xffffffffu, mx1, 1));
        mx1 = fmaxf(mx1, __shfl_xor_sync(0xffffffffu, mx1, 2));
        const float mn0 = fmaxf(m0, mx0);
        const float mn1 = fmaxf(m1, mx1);
        const float a0 = ex2f(m0 - mn0);
        const float a1 = ex2f(m1 - mn1);
        m0 = mn0; m1 = mn1;
        float rs0 = 0.0f, rs1 = 0.0f;
        #pragma unroll
        for (int nt = 0; nt < 8; nt++) {
            acc_s[nt][0] = ex2f(acc_s[nt][0] - mn0);
            acc_s[nt][1] = ex2f(acc_s[nt][1] - mn0);
            acc_s[nt][2] = ex2f(acc_s[nt][2] - mn1);
            acc_s[nt][3] = ex2f(acc_s[nt][3] - mn1);
            rs0 += acc_s[nt][0] + acc_s[nt][1];
            rs1 += acc_s[nt][2] + acc_s[nt][3];
        }
        l0 = l0 * a0 + rs0;
        l1 = l1 * a1 + rs1;
        #pragma unroll
        for (int nt = 0; nt < 8; nt++) {
            acc_o[nt][0] *= a0; acc_o[nt][1] *= a0;
            acc_o[nt][2] *= a1; acc_o[nt][3] *= a1;
        }

        // ---- pack P into fp16 A-fragments (single pass) ----
        uint32_t pfrag[4][4];
        #pragma unroll
        for (int kk = 0; kk < 4; kk++) {
            #pragma unroll
            for (int half = 0; half < 2; half++) {
                const float* e = acc_s[2 * kk + half];
                __half2 h01 = __floats2half2_rn(e[0], e[1]);
                __half2 h23 = __floats2half2_rn(e[2], e[3]);
                pfrag[kk][2 * half]     = *(uint32_t*)&h01;
                pfrag[kk][2 * half + 1] = *(uint32_t*)&h23;
            }
        }

        // ---- O += P V (1 pass) ----
        #pragma unroll
        for (int kk = 0; kk < 4; kk++) {
            const uint32_t cb = ((uint32_t)(kk << 5) + kboff) ^ xorv;
            uint32_t vh4[4][4];
            #pragma unroll
            for (int nt2 = 0; nt2 < 4; nt2++)
                ldmx4(vh4[nt2], stg + 8192 + bRowOff + (nt2 << 11) + cb);
            #pragma unroll
            for (int nt = 0; nt < 8; nt++) {
                const uint32_t b0 = vh4[nt >> 1][(nt & 1) * 2];
                const uint32_t b1 = vh4[nt >> 1][(nt & 1) * 2 + 1];
                mma_f16(acc_o[nt], pfrag[kk], b0, b1);
            }
        }

        __syncthreads();
        if (t + 2 < SQ / 64) issue_kv(t + 2);
        CP_COMMIT();
        CP_WAIT(1);
        __syncthreads();
    }

    // ---- epilogue: normalize, fp16 split, store [b,s,1024] ----
    l0 += __shfl_xor_sync(0xffffffffu, l0, 1);
    l0 += __shfl_xor_sync(0xffffffffu, l0, 2);
    l1 += __shfl_xor_sync(0xffffffffu, l1, 1);
    l1 += __shfl_xor_sync(0xffffffffu, l1, 2);
    const float inv0 = 1.0f / l0;
    const float inv1 = 1.0f / l1;
    const int b = bh >> 4, h = bh & 15;
    const int srow = q0 + wid * 16 + (lane >> 2);
    const size_t ob0 = ((size_t)(b * SQ + srow)) * DH + h * HDIM + 2 * (lane & 3);
    const size_t ob1 = ob0 + 8 * DH;
    #pragma unroll
    for (int nt = 0; nt < 8; nt++) {
        float o0 = acc_o[nt][0] * inv0;
        float o1 = acc_o[nt][1] * inv0;
        float o2 = acc_o[nt][2] * inv1;
        float o3 = acc_o[nt][3] * inv1;
        __half2 h01 = __floats2half2_rn(o0, o1);
        __half2 h23 = __floats2half2_rn(o2, o3);
        float2 f01 = __half22float2(h01);
        float2 f23 = __half22float2(h23);
        __half2 l01 = __floats2half2_rn(o0 - f01.x, o1 - f01.y);
        __half2 l23 = __floats2half2_rn(o2 - f23.x, o3 - f23.y);
        *(uint32_t*)(Oh + ob0 + nt * 8) = *(uint32_t*)&h01;
        *(uint32_t*)(Ol + ob0 + nt * 8) = *(uint32_t*)&l01;
        *(uint32_t*)(Oh + ob1 + nt * 8) = *(uint32_t*)&h23;
        *(uint32_t*)(Ol + ob1 + nt * 8) = *(uint32_t*)&l23;
    }
}

// ---------------------------------------------------------------------------
extern "C" void kernel_launch(void* const* d_in, const int* in_sizes, int n_in,
                              void* d_out, int out_size) {
    const float* x     = (const float*)d_in[0];
    const float* w_qkv = (const float*)d_in[1];
    const float* w_out = (const float*)d_in[2];
    float* out = (float*)d_out;

    __half *xh, *xl, *wqf, *wof, *ah, *al;
    __half *Qh, *Ql, *Kf, *Vf, *Vtf;
    cudaGetSymbolAddress((void**)&xh, g_xh);
    cudaGetSymbolAddress((void**)&xl, g_xl);
    cudaGetSymbolAddress((void**)&wqf, g_wqf);
    cudaGetSymbolAddress((void**)&wof, g_wof);
    cudaGetSymbolAddress((void**)&ah, g_ah);
    cudaGetSymbolAddress((void**)&al, g_al);
    cudaGetSymbolAddress((void**)&Qh, g_Qh);
    cudaGetSymbolAddress((void**)&Ql, g_Ql);
    cudaGetSymbolAddress((void**)&Kf, g_Kf);
    cudaGetSymbolAddress((void**)&Vf, g_Vf);
    cudaGetSymbolAddress((void**)&Vtf, g_Vtf);

    cudaFuncSetAttribute(gemm_mma, cudaFuncAttributeMaxDynamicSharedMemorySize,
                         GSM_TOTAL);
    cudaFuncSetAttribute(gemm_qkv, cudaFuncAttributeMaxDynamicSharedMemorySize,
                         GSM_TOTAL);
    cudaFuncSetAttribute(attn_mma, cudaFuncAttributeMaxDynamicSharedMemorySize,
                         ATT_SMEM);

    const int M = BZ * SQ;                 // 4096
    const int nX  = M * DH / 4;            // 1048576
    const int nWq = 3 * DH * DH / 4;       // 786432
    const int nWo = DH * DH / 4;           // 262144
    const int nTot = nX + nWq + nWo;

    // 0) input/weight conversion (single launch)
    prep_in<<<(nTot + 255) / 256, 256>>>((const float4*)x, (const float4*)w_qkv,
                                         (const float4*)w_out,
                                         (uint2*)xh, (uint2*)xl,
                                         (uint2*)wqf, (uint2*)wof,
                                         nX, nWq, nWo);

    // 1) QKV projection, fused epilogue -> head-major fp16 Q(split)/K/V
    gemm_qkv<<<dim3(3 * DH / 128, M / 128), 256, GSM_TOTAL>>>(
        xh, xl, wqf, Qh, Ql, Kf, Vf, M, 3 * DH, DH);

    // 2) V transpose -> [bh,64,s]
    transp_v<<<dim3(SQ / 64, BZ * NH), 256>>>(Vf, Vtf);

    // 3) attention -> fp16 hi/lo [b,s,1024]
    attn_mma<<<dim3(SQ / 128, BZ * NH), 256, ATT_SMEM>>>(Qh, Ql, Kf, Vtf,
                                                         ah, al);

    // 4) output projection -> d_out (fp32)
    gemm_mma<<<dim3(DH / 128, M / 128), 256, GSM_TOTAL>>>(ah, al, wof, out,
                                                          M, DH, DH);
}

// round 10
// speedup vs baseline: 2.1662x; 1.0181x over previous
#include <cuda_runtime.h>
#include <cuda_bf16.h>
#include <cuda_fp16.h>
#include <cstdint>

// Problem constants
#define BZ 2
#define SQ 2048
#define DH 1024
#define NH 16
#define HDIM 64

// 0.125 * log2(e): folded into Q so softmax runs in the exp2 domain
#define SCALE_LOG2 0.18033688011112042f

// ---------------------------------------------------------------------------
// Scratch (no cudaMalloc allowed)
// ---------------------------------------------------------------------------
__device__ __align__(16) __half g_xh[(size_t)BZ * SQ * DH];
__device__ __align__(16) __half g_xl[(size_t)BZ * SQ * DH];
__device__ __align__(16) __half g_wqf[(size_t)3 * DH * DH];
__device__ __align__(16) __half g_wof[(size_t)DH * DH];
// head-major attention operands (fp16)
__device__ __align__(16) __half g_Qh[(size_t)BZ * NH * SQ * HDIM];
__device__ __align__(16) __half g_Ql[(size_t)BZ * NH * SQ * HDIM];
__device__ __align__(16) __half g_Kf[(size_t)BZ * NH * SQ * HDIM];
__device__ __align__(16) __half g_Vf[(size_t)BZ * NH * SQ * HDIM];   // [bh,s,64]
__device__ __align__(16) __half g_Vtf[(size_t)BZ * NH * HDIM * SQ];  // [bh,64,s]
// attention output (fp16 split, [b,s,1024])
__device__ __align__(16) __half g_ah[(size_t)BZ * SQ * DH];
__device__ __align__(16) __half g_al[(size_t)BZ * SQ * DH];

// ---------------------------------------------------------------------------
// Portable PTX helpers (sm_80+ subset; no arch-"a" features)
// ---------------------------------------------------------------------------
__device__ __forceinline__ uint32_t smem_to_u32(const void* p) {
    uint32_t a;
    asm("{ .reg .u64 t; cvta.to.shared.u64 t, %1; cvt.u32.u64 %0, t; }"
        : "=r"(a) : "l"(p));
    return a;
}

__device__ __forceinline__ void cp16(uint32_t saddr, const void* gaddr) {
    asm volatile("cp.async.cg.shared.global [%0], [%1], 16;"
                 :: "r"(saddr), "l"(gaddr));
}
#define CP_COMMIT() asm volatile("cp.async.commit_group;" ::: "memory")
#define CP_WAIT(n)  asm volatile("cp.async.wait_group %0;" :: "n"(n) : "memory")

__device__ __forceinline__ void ldmx4(uint32_t* r, uint32_t addr) {
    asm volatile("ldmatrix.sync.aligned.m8n8.x4.shared.b16 {%0,%1,%2,%3}, [%4];"
                 : "=r"(r[0]), "=r"(r[1]), "=r"(r[2]), "=r"(r[3]) : "r"(addr));
}

__device__ __forceinline__ void mma_f16(float* d, const uint32_t* a,
                                        uint32_t b0, uint32_t b1) {
    asm volatile(
        "mma.sync.aligned.m16n8k16.row.col.f32.f16.f16.f32 "
        "{%0,%1,%2,%3}, {%4,%5,%6,%7}, {%8,%9}, {%0,%1,%2,%3};"
        : "+f"(d[0]), "+f"(d[1]), "+f"(d[2]), "+f"(d[3])
        : "r"(a[0]), "r"(a[1]), "r"(a[2]), "r"(a[3]), "r"(b0), "r"(b1));
}

__device__ __forceinline__ float ex2f(float x) {
    float r;
    asm("ex2.approx.f32 %0, %1;" : "=f"(r) : "f"(x));
    return r;
}

__device__ __forceinline__ void split4h(float4 v, uint2& hi, uint2& lo) {
    union { __half b[4]; uint2 u; } H, L;
    float f[4] = {v.x, v.y, v.z, v.w};
    #pragma unroll
    for (int j = 0; j < 4; j++) {
        __half h = __float2half_rn(f[j]);
        H.b[j] = h;
        L.b[j] = __float2half_rn(f[j] - __half2float(h));
    }
    hi = H.u; lo = L.u;
}

__device__ __forceinline__ uint2 pack4h(float4 v) {
    union { __half b[4]; uint2 u; } H;
    H.b[0] = __float2half_rn(v.x);
    H.b[1] = __float2half_rn(v.y);
    H.b[2] = __float2half_rn(v.z);
    H.b[3] = __float2half_rn(v.w);
    return H.u;
}

// ---------------------------------------------------------------------------
// prep_in: one kernel for x split + both weight packs (index-ranged)
// ---------------------------------------------------------------------------
__global__ void prep_in(const float4* __restrict__ x,
                        const float4* __restrict__ wq,
                        const float4* __restrict__ wo,
                        uint2* __restrict__ xh, uint2* __restrict__ xl,
                        uint2* __restrict__ wqf, uint2* __restrict__ wof,
                        int nX, int nWq, int nWo) {
    int i = blockIdx.x * blockDim.x + threadIdx.x;
    if (i < nX) {
        uint2 H, L;
        split4h(x[i], H, L);
        xh[i] = H; xl[i] = L;
    } else if (i < nX + nWq) {
        wqf[i - nX] = pack4h(wq[i - nX]);
    } else if (i < nX + nWq + nWo) {
        wof[i - nX - nWq] = pack4h(wo[i - nX - nWq]);
    }
}

// ---------------------------------------------------------------------------
// transp_v: V [bh,s,64] fp16 -> Vt [bh,64,s] fp16 (64x64 smem tiles)
// ---------------------------------------------------------------------------
__global__ void transp_v(const __half* __restrict__ Vf, __half* __restrict__ Vtf) {
    __shared__ __half Vs[64][72];
    const int bh = blockIdx.y;
    const int s0 = blockIdx.x * 64;
    const int tid = threadIdx.x;
    const size_t src = ((size_t)bh * SQ + s0) * HDIM;
    #pragma unroll
    for (int it = 0; it < 2; it++) {
        int lin = it * 256 + tid;
        int row = lin >> 3;
        int c8 = lin & 7;
        union { uint4 u; __half h[8]; } t;
        t.u = *(const uint4*)(Vf + src + (size_t)row * HDIM + c8 * 8);
        #pragma unroll
        for (int j = 0; j < 8; j++) Vs[row][c8 * 8 + j] = t.h[j];
    }
    __syncthreads();
    #pragma unroll
    for (int it = 0; it < 2; it++) {
        int lin = it * 256 + tid;
        int hd = lin >> 3;
        int c8 = lin & 7;
        union { uint4 u; __half h[8]; } t;
        #pragma unroll
        for (int j = 0; j < 8; j++) t.h[j] = Vs[c8 * 8 + j][hd];
        *(uint4*)(Vtf + ((size_t)bh * HDIM + hd) * SQ + s0 + c8 * 8) = t.u;
    }
}

// ---------------------------------------------------------------------------
// Shared GEMM mainloop config (R8-proven): CTA 128x128, K-chunk 32,
// 2 stages x 24KB = 48KB -> 2 CTAs/SM. 256 threads, warps 4(m) x 2(n),
// warp tile 32x64. Rows 64B; swizzle off ^ ((off>>3)&0x30).
// ---------------------------------------------------------------------------
#define G_STAGE 24576
#define GSM_TOTAL (2 * G_STAGE)

template <int FUSED_QKV>
__device__ __forceinline__ void gemm_body(
    const __half* __restrict__ Ah, const __half* __restrict__ Al,
    const __half* __restrict__ Bf,
    float* __restrict__ C,
    __half* __restrict__ Qh, __half* __restrict__ Ql,
    __half* __restrict__ Kf, __half* __restrict__ Vf,
    int M, int N, int K, char* smem) {
    const uint32_t sb = smem_to_u32(smem);
    const int tid = threadIdx.x;
    const int lane = tid & 31;
    const int wid = tid >> 5;
    const int bm = blockIdx.y * 128;
    const int bn = blockIdx.x * 128;
    const int wm = (wid >> 1) * 32;   // 4 m-warps
    const int wn = (wid & 1) * 64;    // 2 n-warps

    auto issue_stage = [&](int ch) {
        const int k0 = ch << 5;
        const uint32_t buf = sb + (uint32_t)(ch & 1) * G_STAGE;
        #pragma unroll
        for (int i = 0; i < 2; i++) {
            int lin = tid + (i << 8);
            int row = lin >> 2;
            int c4 = lin & 3;
            uint32_t off = (uint32_t)(row << 6) + (uint32_t)(c4 << 4);
            uint32_t sw = off ^ ((off >> 3) & 0x30);
            size_t ga = (size_t)(bm + row) * K + k0 + (c4 << 3);
            size_t gb = (size_t)(bn + row) * K + k0 + (c4 << 3);
            cp16(buf + sw,         Ah + ga);
            cp16(buf + 8192 + sw,  Al + ga);
            cp16(buf + 16384 + sw, Bf + gb);
        }
    };

    const uint32_t xorv   = (uint32_t)(lane & 6) << 3;
    const uint32_t aRowOff = (uint32_t)((wm + (lane & 15)) << 6);
    const uint32_t kaoff  = (uint32_t)((lane >> 4) << 4);
    const uint32_t bRowOff =
        (uint32_t)((wn + (lane & 7) + (((lane >> 4) & 1) << 3)) << 6);
    const uint32_t kboff  = (uint32_t)(((lane >> 3) & 1) << 4);

    float acc[2][8][4] = {};

    const int KCHUNKS = K >> 5;
    issue_stage(0); CP_COMMIT();

    for (int ch = 0; ch < KCHUNKS; ch++) {
        CP_WAIT(0);
        __syncthreads();
        if (ch + 1 < KCHUNKS) issue_stage(ch + 1);
        CP_COMMIT();

        const uint32_t buf = sb + (uint32_t)(ch & 1) * G_STAGE;
        const uint32_t aHi = buf + aRowOff;
        const uint32_t aLo = aHi + 8192;
        const uint32_t bF  = buf + 16384 + bRowOff;

        #pragma unroll
        for (int s = 0; s < 2; s++) {
            const uint32_t ca = ((uint32_t)(s << 5) + kaoff) ^ xorv;
            const uint32_t cb = ((uint32_t)(s << 5) + kboff) ^ xorv;
            uint32_t ah4[2][4], al4[2][4], b4[4][4];
            #pragma unroll
            for (int mt = 0; mt < 2; mt++) {
                ldmx4(ah4[mt], aHi + (mt << 10) + ca);
                ldmx4(al4[mt], aLo + (mt << 10) + ca);
            }
            #pragma unroll
            for (int nt2 = 0; nt2 < 4; nt2++)
                ldmx4(b4[nt2], bF + (nt2 << 10) + cb);
            #pragma unroll
            for (int mt = 0; mt < 2; mt++)
                #pragma unroll
                for (int nt = 0; nt < 8; nt++) {
                    const uint32_t b0 = b4[nt >> 1][(nt & 1) * 2];
                    const uint32_t b1 = b4[nt >> 1][(nt & 1) * 2 + 1];
                    mma_f16(acc[mt][nt], ah4[mt], b0, b1);
                    mma_f16(acc[mt][nt], al4[mt], b0, b1);
                }
        }
    }

    if (FUSED_QKV) {
        const int region = bn >> 10;     // 0=Q, 1=K, 2=V
        const int cbase = (bn & 1023) + wn;
        #pragma unroll
        for (int mt = 0; mt < 2; mt++) {
            #pragma unroll
            for (int hr = 0; hr < 2; hr++) {
                const int r = bm + wm + mt * 16 + (lane >> 2) + hr * 8;
                const int bb = r >> 11, ss = r & (SQ - 1);
                #pragma unroll
                for (int nt = 0; nt < 8; nt++) {
                    const int cc = cbase + nt * 8 + (lane & 3) * 2;
                    const int h = cc >> 6, d = cc & 63;
                    const size_t idx =
                        (((size_t)(bb * NH + h) * SQ + ss) << 6) + d;
                    float v0 = acc[mt][nt][hr * 2 + 0];
                    float v1 = acc[mt][nt][hr * 2 + 1];
                    if (region == 0) {
                        v0 *= SCALE_LOG2; v1 *= SCALE_LOG2;
                        __half2 hh = __floats2half2_rn(v0, v1);
                        float2 ff = __half22float2(hh);
                        __half2 ll = __floats2half2_rn(v0 - ff.x, v1 - ff.y);
                        *(uint32_t*)(Qh + idx) = *(uint32_t*)&hh;
                        *(uint32_t*)(Ql + idx) = *(uint32_t*)&ll;
                    } else if (region == 1) {
                        __half2 hh = __floats2half2_rn(v0, v1);
                        *(uint32_t*)(Kf + idx) = *(uint32_t*)&hh;
                    } else {
                        __half2 hh = __floats2half2_rn(v0, v1);
                        *(uint32_t*)(Vf + idx) = *(uint32_t*)&hh;
                    }
                }
            }
        }
    } else {
        #pragma unroll
        for (int mt = 0; mt < 2; mt++) {
            const int r0 = bm + wm + mt * 16 + (lane >> 2);
            #pragma unroll
            for (int nt = 0; nt < 8; nt++) {
                const int c = bn + wn + nt * 8 + (lane & 3) * 2;
                float2 v0 = make_float2(acc[mt][nt][0], acc[mt][nt][1]);
                float2 v1 = make_float2(acc[mt][nt][2], acc[mt][nt][3]);
                *(float2*)&C[(size_t)r0 * N + c]       = v0;
                *(float2*)&C[(size_t)(r0 + 8) * N + c] = v1;
            }
        }
    }
}

__global__ void __launch_bounds__(256, 2) gemm_mma(
    const __half* __restrict__ Ah, const __half* __restrict__ Al,
    const __half* __restrict__ Bf,
    float* __restrict__ C, int M, int N, int K) {
    extern __shared__ char smem[];
    gemm_body<0>(Ah, Al, Bf, C, nullptr, nullptr, nullptr, nullptr,
                 M, N, K, smem);
}

__global__ void __launch_bounds__(256, 2) gemm_qkv(
    const __half* __restrict__ Ah, const __half* __restrict__ Al,
    const __half* __restrict__ Bf,
    __half* __restrict__ Qh, __half* __restrict__ Ql,
    __half* __restrict__ Kf, __half* __restrict__ Vf,
    int M, int N, int K) {
    extern __shared__ char smem[];
    gemm_body<1>(Ah, Al, Bf, nullptr, Qh, Ql, Kf, Vf, M, N, K, smem);
}

// ---------------------------------------------------------------------------
// fp16 tensor-core flash attention — R10: 2 CTAs/SM.
// Register diet: Qh in regs (16); Ql persistent in smem, re-ldmatrix'd per
// tile; pfrag packed into dead acc_s slots; kh4/vh4 consumed per n-pair.
// smem 48KB/CTA: [0,16K) Ql | [16K,48K) 2 KV stages {K 8K | Vt 8K}.
// ---------------------------------------------------------------------------
#define A_STAGE 16384
#define ATT_SMEM 49152

__global__ void __launch_bounds__(256, 2) attn_mma(
    const __half* __restrict__ Qh, const __half* __restrict__ Ql,
    const __half* __restrict__ Kf, const __half* __restrict__ Vtf,
    __half* __restrict__ Oh, __half* __restrict__ Ol) {
    extern __shared__ char smem[];
    const uint32_t sb = smem_to_u32(smem);
    const int tid = threadIdx.x;
    const int lane = tid & 31;
    const int wid = tid >> 5;
    const int bh = blockIdx.y;
    const int q0 = blockIdx.x * 128;

    const size_t qbase = ((size_t)bh * SQ + q0) * HDIM;
    const size_t kbase = (size_t)bh * SQ * HDIM;
    const size_t vbase = (size_t)bh * HDIM * SQ;

    // prologue loader: Ql -> [0,16K) persistent; Qh staged at [16K,32K)
    auto issue_q = [&]() {
        #pragma unroll
        for (int i = 0; i < 4; i++) {
            int lin = tid + (i << 8);
            int row = lin >> 3;
            int c8 = lin & 7;
            uint32_t off = (uint32_t)(row << 7) + (uint32_t)(c8 << 4);
            uint32_t sw = off ^ ((off >> 3) & 0x70);
            size_t g = qbase + (size_t)row * HDIM + (c8 << 3);
            cp16(sb + sw,         Ql + g);
            cp16(sb + 16384 + sw, Qh + g);
        }
    };
    auto issue_kv = [&](int t) {
        const int kv0 = t << 6;
        const uint32_t stg = sb + 16384 + (uint32_t)(t & 1) * A_STAGE;
        #pragma unroll
        for (int i = 0; i < 2; i++) {
            int lin = tid + (i << 8);
            int row = lin >> 3;
            int c8 = lin & 7;
            uint32_t off = (uint32_t)(row << 7) + (uint32_t)(c8 << 4);
            uint32_t sw = off ^ ((off >> 3) & 0x70);
            size_t gk = kbase + (size_t)(kv0 + row) * HDIM + (c8 << 3);
            size_t gv = vbase + (size_t)row * SQ + kv0 + (c8 << 3);
            cp16(stg + sw,        Kf + gk);
            cp16(stg + 8192 + sw, Vtf + gv);
        }
    };

    const uint32_t xorv = (uint32_t)(lane & 7) << 4;
    const uint32_t qRowOff = (uint32_t)(((wid << 4) + (lane & 15)) << 7);
    const uint32_t kaoff = (uint32_t)((lane >> 4) << 4);
    const uint32_t bRowOff =
        (uint32_t)(((lane & 7) + (((lane >> 4) & 1) << 3)) << 7);
    const uint32_t kboff = (uint32_t)(((lane >> 3) & 1) << 4);

    // ---- prologue ----
    issue_q(); CP_COMMIT();
    CP_WAIT(0);
    __syncthreads();

    uint32_t qh[4][4];
    #pragma unroll
    for (int kk = 0; kk < 4; kk++) {
        const uint32_t ca = ((uint32_t)(kk << 5) + kaoff) ^ xorv;
        ldmx4(qh[kk], sb + 16384 + qRowOff + ca);
    }
    __syncthreads();            // Qh staging area free for KV

    issue_kv(0); CP_COMMIT();
    issue_kv(1); CP_COMMIT();
    CP_WAIT(1);
    __syncthreads();

    float m0 = -1e30f, m1 = -1e30f, l0 = 0.0f, l1 = 0.0f;
    float acc_o[8][4] = {};

    for (int t = 0; t < SQ / 64; t++) {
        const uint32_t stg = sb + 16384 + (uint32_t)(t & 1) * A_STAGE;

        // ---- S = Q K^T (2 passes: Qh(regs) + Ql(smem reload)) ----
        float acc_s[8][4] = {};
        #pragma unroll
        for (int kk = 0; kk < 4; kk++) {
            const uint32_t ca = ((uint32_t)(kk << 5) + kaoff) ^ xorv;
            const uint32_t cb = ((uint32_t)(kk << 5) + kboff) ^ xorv;
            uint32_t ql4[4];
            ldmx4(ql4, sb + qRowOff + ca);
            #pragma unroll
            for (int nt2 = 0; nt2 < 4; nt2++) {
                uint32_t k4[4];
                ldmx4(k4, stg + bRowOff + (nt2 << 11) + cb);
                #pragma unroll
                for (int j = 0; j < 2; j++) {
                    const int nt = 2 * nt2 + j;
                    mma_f16(acc_s[nt], qh[kk], k4[j * 2], k4[j * 2 + 1]);
                    mma_f16(acc_s[nt], ql4,    k4[j * 2], k4[j * 2 + 1]);
                }
            }
        }

        // ---- online softmax (log2 domain) ----
        float mx0 = -1e30f, mx1 = -1e30f;
        #pragma unroll
        for (int nt = 0; nt < 8; nt++) {
            mx0 = fmaxf(mx0, fmaxf(acc_s[nt][0], acc_s[nt][1]));
            mx1 = fmaxf(mx1, fmaxf(acc_s[nt][2], acc_s[nt][3]));
        }
        mx0 = fmaxf(mx0, __shfl_xor_sync(0xffffffffu, mx0, 1));
        mx0 = fmaxf(mx0, __shfl_xor_sync(0xffffffffu, mx0, 2));
        mx1 = fmaxf(mx1, __shfl_xor_sync(0xffffffffu, mx1, 1));
        mx1 = fmaxf(mx1, __shfl_xor_sync(0xffffffffu, mx1, 2));
        const float mn0 = fmaxf(m0, mx0);
        const float mn1 = fmaxf(m1, mx1);
        const float a0 = ex2f(m0 - mn0);
        const float a1 = ex2f(m1 - mn1);
        m0 = mn0; m1 = mn1;
        float rs0 = 0.0f, rs1 = 0.0f;
        // exp + pack P into the low slots of acc_s (slots 0,1 hold bits after)
        #pragma unroll
        for (int nt = 0; nt < 8; nt++) {
            float e0 = ex2f(acc_s[nt][0] - mn0);
            float e1 = ex2f(acc_s[nt][1] - mn0);
            float e2 = ex2f(acc_s[nt][2] - mn1);
            float e3 = ex2f(acc_s[nt][3] - mn1);
            rs0 += e0 + e1;
            rs1 += e2 + e3;
            __half2 h01 = __floats2half2_rn(e0, e1);
            __half2 h23 = __floats2half2_rn(e2, e3);
            acc_s[nt][0] = __uint_as_float(*(uint32_t*)&h01);
            acc_s[nt][1] = __uint_as_float(*(uint32_t*)&h23);
        }
        l0 = l0 * a0 + rs0;
        l1 = l1 * a1 + rs1;
        #pragma unroll
        for (int nt = 0; nt < 8; nt++) {
            acc_o[nt][0] *= a0; acc_o[nt][1] *= a0;
            acc_o[nt][2] *= a1; acc_o[nt][3] *= a1;
        }

        // ---- O += P V (1 pass; P fragments from acc_s bit slots) ----
        #pragma unroll
        for (int kk = 0; kk < 4; kk++) {
            uint32_t pf[4];
            pf[0] = __float_as_uint(acc_s[2 * kk][0]);
            pf[1] = __float_as_uint(acc_s[2 * kk][1]);
            pf[2] = __float_as_uint(acc_s[2 * kk + 1][0]);
            pf[3] = __float_as_uint(acc_s[2 * kk + 1][1]);
            const uint32_t cb = ((uint32_t)(kk << 5) + kboff) ^ xorv;
            #pragma unroll
            for (int nt2 = 0; nt2 < 4; nt2++) {
                uint32_t v4[4];
                ldmx4(v4, stg + 8192 + bRowOff + (nt2 << 11) + cb);
                #pragma unroll
                for (int j = 0; j < 2; j++) {
                    const int nt = 2 * nt2 + j;
                    mma_f16(acc_o[nt], pf, v4[j * 2], v4[j * 2 + 1]);
                }
            }
        }

        __syncthreads();
        if (t + 2 < SQ / 64) issue_kv(t + 2);
        CP_COMMIT();
        CP_WAIT(1);
        __syncthreads();
    }

    // ---- epilogue: normalize, fp16 split, store [b,s,1024] ----
    l0 += __shfl_xor_sync(0xffffffffu, l0, 1);
    l0 += __shfl_xor_sync(0xffffffffu, l0, 2);
    l1 += __shfl_xor_sync(0xffffffffu, l1, 1);
    l1 += __shfl_xor_sync(0xffffffffu, l1, 2);
    const float inv0 = 1.0f / l0;
    const float inv1 = 1.0f / l1;
    const int b = bh >> 4, h = bh & 15;
    const int srow = q0 + wid * 16 + (lane >> 2);
    const size_t ob0 = ((size_t)(b * SQ + srow)) * DH + h * HDIM + 2 * (lane & 3);
    const size_t ob1 = ob0 + 8 * DH;
    #pragma unroll
    for (int nt = 0; nt < 8; nt++) {
        float o0 = acc_o[nt][0] * inv0;
        float o1 = acc_o[nt][1] * inv0;
        float o2 = acc_o[nt][2] * inv1;
        float o3 = acc_o[nt][3] * inv1;
        __half2 h01 = __floats2half2_rn(o0, o1);
        __half2 h23 = __floats2half2_rn(o2, o3);
        float2 f01 = __half22float2(h01);
        float2 f23 = __half22float2(h23);
        __half2 l01 = __floats2half2_rn(o0 - f01.x, o1 - f01.y);
        __half2 l23 = __floats2half2_rn(o2 - f23.x, o3 - f23.y);
        *(uint32_t*)(Oh + ob0 + nt * 8) = *(uint32_t*)&h01;
        *(uint32_t*)(Ol + ob0 + nt * 8) = *(uint32_t*)&l01;
        *(uint32_t*)(Oh + ob1 + nt * 8) = *(uint32_t*)&h23;
        *(uint32_t*)(Ol + ob1 + nt * 8) = *(uint32_t*)&l23;
    }
}

// ---------------------------------------------------------------------------
extern "C" void kernel_launch(void* const* d_in, const int* in_sizes, int n_in,
                              void* d_out, int out_size) {
    const float* x     = (const float*)d_in[0];
    const float* w_qkv = (const float*)d_in[1];
    const float* w_out = (const float*)d_in[2];
    float* out = (float*)d_out;

    __half *xh, *xl, *wqf, *wof, *ah, *al;
    __half *Qh, *Ql, *Kf, *Vf, *Vtf;
    cudaGetSymbolAddress((void**)&xh, g_xh);
    cudaGetSymbolAddress((void**)&xl, g_xl);
    cudaGetSymbolAddress((void**)&wqf, g_wqf);
    cudaGetSymbolAddress((void**)&wof, g_wof);
    cudaGetSymbolAddress((void**)&ah, g_ah);
    cudaGetSymbolAddress((void**)&al, g_al);
    cudaGetSymbolAddress((void**)&Qh, g_Qh);
    cudaGetSymbolAddress((void**)&Ql, g_Ql);
    cudaGetSymbolAddress((void**)&Kf, g_Kf);
    cudaGetSymbolAddress((void**)&Vf, g_Vf);
    cudaGetSymbolAddress((void**)&Vtf, g_Vtf);

    cudaFuncSetAttribute(gemm_mma, cudaFuncAttributeMaxDynamicSharedMemorySize,
                         GSM_TOTAL);
    cudaFuncSetAttribute(gemm_qkv, cudaFuncAttributeMaxDynamicSharedMemorySize,
                         GSM_TOTAL);
    cudaFuncSetAttribute(attn_mma, cudaFuncAttributeMaxDynamicSharedMemorySize,
                         ATT_SMEM);

    const int M = BZ * SQ;                 // 4096
    const int nX  = M * DH / 4;
    const int nWq = 3 * DH * DH / 4;
    const int nWo = DH * DH / 4;
    const int nTot = nX + nWq + nWo;

    // 0) input/weight conversion (single launch)
    prep_in<<<(nTot + 255) / 256, 256>>>((const float4*)x, (const float4*)w_qkv,
                                         (const float4*)w_out,
                                         (uint2*)xh, (uint2*)xl,
                                         (uint2*)wqf, (uint2*)wof,
                                         nX, nWq, nWo);

    // 1) QKV projection, fused epilogue -> head-major fp16 Q(split)/K/V
    gemm_qkv<<<dim3(3 * DH / 128, M / 128), 256, GSM_TOTAL>>>(
        xh, xl, wqf, Qh, Ql, Kf, Vf, M, 3 * DH, DH);

    // 2) V transpose -> [bh,64,s]
    transp_v<<<dim3(SQ / 64, BZ * NH), 256>>>(Vf, Vtf);

    // 3) attention -> fp16 hi/lo [b,s,1024]
    attn_mma<<<dim3(SQ / 128, BZ * NH), 256, ATT_SMEM>>>(Qh, Ql, Kf, Vtf,
                                                         ah, al);

    // 4) output projection -> d_out (fp32)
    gemm_mma<<<dim3(DH / 128, M / 128), 256, GSM_TOTAL>>>(ah, al, wof, out,
                                                          M, DH, DH);
}

// round 11
// speedup vs baseline: 2.9739x; 1.3729x over previous
#include <cuda_runtime.h>
#include <cuda_bf16.h>
#include <cuda_fp16.h>
#include <cstdint>

// Problem constants
#define BZ 2
#define SQ 2048
#define DH 1024
#define NH 16
#define HDIM 64

// 0.125 * log2(e): folded into Q so softmax runs in the exp2 domain
#define SCALE_LOG2 0.18033688011112042f

// ---------------------------------------------------------------------------
// Scratch (no cudaMalloc allowed)
// ---------------------------------------------------------------------------
__device__ __align__(16) __half g_xf[(size_t)BZ * SQ * DH];
__device__ __align__(16) __half g_wqf[(size_t)3 * DH * DH];
__device__ __align__(16) __half g_wof[(size_t)DH * DH];
// head-major attention operands (fp16)
__device__ __align__(16) __half g_Qf[(size_t)BZ * NH * SQ * HDIM];
__device__ __align__(16) __half g_Kf[(size_t)BZ * NH * SQ * HDIM];
__device__ __align__(16) __half g_Vf[(size_t)BZ * NH * SQ * HDIM];   // [bh,s,64]
__device__ __align__(16) __half g_Vtf[(size_t)BZ * NH * HDIM * SQ];  // [bh,64,s]
// attention output (fp16 split, [b,s,1024]) — out-proj stays 2-pass
__device__ __align__(16) __half g_ah[(size_t)BZ * SQ * DH];
__device__ __align__(16) __half g_al[(size_t)BZ * SQ * DH];

// ---------------------------------------------------------------------------
// Portable PTX helpers (sm_80+ subset; no arch-"a" features)
// ---------------------------------------------------------------------------
__device__ __forceinline__ uint32_t smem_to_u32(const void* p) {
    uint32_t a;
    asm("{ .reg .u64 t; cvta.to.shared.u64 t, %1; cvt.u32.u64 %0, t; }"
        : "=r"(a) : "l"(p));
    return a;
}

__device__ __forceinline__ void cp16(uint32_t saddr, const void* gaddr) {
    asm volatile("cp.async.cg.shared.global [%0], [%1], 16;"
                 :: "r"(saddr), "l"(gaddr));
}
#define CP_COMMIT() asm volatile("cp.async.commit_group;" ::: "memory")
#define CP_WAIT(n)  asm volatile("cp.async.wait_group %0;" :: "n"(n) : "memory")

__device__ __forceinline__ void ldmx4(uint32_t* r, uint32_t addr) {
    asm volatile("ldmatrix.sync.aligned.m8n8.x4.shared.b16 {%0,%1,%2,%3}, [%4];"
                 : "=r"(r[0]), "=r"(r[1]), "=r"(r[2]), "=r"(r[3]) : "r"(addr));
}

__device__ __forceinline__ void mma_f16(float* d, const uint32_t* a,
                                        uint32_t b0, uint32_t b1) {
    asm volatile(
        "mma.sync.aligned.m16n8k16.row.col.f32.f16.f16.f32 "
        "{%0,%1,%2,%3}, {%4,%5,%6,%7}, {%8,%9}, {%0,%1,%2,%3};"
        : "+f"(d[0]), "+f"(d[1]), "+f"(d[2]), "+f"(d[3])
        : "r"(a[0]), "r"(a[1]), "r"(a[2]), "r"(a[3]), "r"(b0), "r"(b1));
}

__device__ __forceinline__ float ex2f(float x) {
    float r;
    asm("ex2.approx.f32 %0, %1;" : "=f"(r) : "f"(x));
    return r;
}

__device__ __forceinline__ void split4h(float4 v, uint2& hi, uint2& lo) {
    union { __half b[4]; uint2 u; } H, L;
    float f[4] = {v.x, v.y, v.z, v.w};
    #pragma unroll
    for (int j = 0; j < 4; j++) {
        __half h = __float2half_rn(f[j]);
        H.b[j] = h;
        L.b[j] = __float2half_rn(f[j] - __half2float(h));
    }
    hi = H.u; lo = L.u;
}

__device__ __forceinline__ uint2 pack4h(float4 v) {
    union { __half b[4]; uint2 u; } H;
    H.b[0] = __float2half_rn(v.x);
    H.b[1] = __float2half_rn(v.y);
    H.b[2] = __float2half_rn(v.z);
    H.b[3] = __float2half_rn(v.w);
    return H.u;
}

// ---------------------------------------------------------------------------
// prep_in: pack x / w_qkv / w_out to plain fp16 (index-ranged, one launch)
// ---------------------------------------------------------------------------
__global__ void prep_in(const float4* __restrict__ x,
                        const float4* __restrict__ wq,
                        const float4* __restrict__ wo,
                        uint2* __restrict__ xf,
                        uint2* __restrict__ wqf, uint2* __restrict__ wof,
                        int nX, int nWq, int nWo) {
    int i = blockIdx.x * blockDim.x + threadIdx.x;
    if (i < nX) {
        xf[i] = pack4h(x[i]);
    } else if (i < nX + nWq) {
        wqf[i - nX] = pack4h(wq[i - nX]);
    } else if (i < nX + nWq + nWo) {
        wof[i - nX - nWq] = pack4h(wo[i - nX - nWq]);
    }
}

// ---------------------------------------------------------------------------
// transp_v: V [bh,s,64] fp16 -> Vt [bh,64,s] fp16 (64x64 smem tiles)
// ---------------------------------------------------------------------------
__global__ void transp_v(const __half* __restrict__ Vf, __half* __restrict__ Vtf) {
    __shared__ __half Vs[64][72];
    const int bh = blockIdx.y;
    const int s0 = blockIdx.x * 64;
    const int tid = threadIdx.x;
    const size_t src = ((size_t)bh * SQ + s0) * HDIM;
    #pragma unroll
    for (int it = 0; it < 2; it++) {
        int lin = it * 256 + tid;
        int row = lin >> 3;
        int c8 = lin & 7;
        union { uint4 u; __half h[8]; } t;
        t.u = *(const uint4*)(Vf + src + (size_t)row * HDIM + c8 * 8);
        #pragma unroll
        for (int j = 0; j < 8; j++) Vs[row][c8 * 8 + j] = t.h[j];
    }
    __syncthreads();
    #pragma unroll
    for (int it = 0; it < 2; it++) {
        int lin = it * 256 + tid;
        int hd = lin >> 3;
        int c8 = lin & 7;
        union { uint4 u; __half h[8]; } t;
        #pragma unroll
        for (int j = 0; j < 8; j++) t.h[j] = Vs[c8 * 8 + j][hd];
        *(uint4*)(Vtf + ((size_t)bh * HDIM + hd) * SQ + s0 + c8 * 8) = t.u;
    }
}

// ---------------------------------------------------------------------------
// GEMM tiling (shared by both GEMMs): CTA 128x128, K-chunk 32, 2 stages,
// 256 threads, warps 4(m) x 2(n), warp tile 32x64.
// Rows 64B; swizzle off ^ ((off>>3)&0x30).
// ---------------------------------------------------------------------------

// ---- 1-pass QKV GEMM, fused head-major epilogue -------------------------
// stage: Af 8K | Bf 8K = 16KB; 2 stages = 32KB; 2 CTAs/SM.
#define GQ_STAGE 16384
#define GQ_TOTAL (2 * GQ_STAGE)

__global__ void __launch_bounds__(256, 2) gemm_qkv(
    const __half* __restrict__ Af, const __half* __restrict__ Bf,
    __half* __restrict__ Qf, __half* __restrict__ Kf, __half* __restrict__ Vf,
    int M, int N, int K) {
    extern __shared__ char smem[];
    const uint32_t sb = smem_to_u32(smem);
    const int tid = threadIdx.x;
    const int lane = tid & 31;
    const int wid = tid >> 5;
    const int bm = blockIdx.y * 128;
    const int bn = blockIdx.x * 128;
    const int wm = (wid >> 1) * 32;
    const int wn = (wid & 1) * 64;

    auto issue_stage = [&](int ch) {
        const int k0 = ch << 5;
        const uint32_t buf = sb + (uint32_t)(ch & 1) * GQ_STAGE;
        #pragma unroll
        for (int i = 0; i < 2; i++) {
            int lin = tid + (i << 8);
            int row = lin >> 2;
            int c4 = lin & 3;
            uint32_t off = (uint32_t)(row << 6) + (uint32_t)(c4 << 4);
            uint32_t sw = off ^ ((off >> 3) & 0x30);
            size_t ga = (size_t)(bm + row) * K + k0 + (c4 << 3);
            size_t gb = (size_t)(bn + row) * K + k0 + (c4 << 3);
            cp16(buf + sw,        Af + ga);
            cp16(buf + 8192 + sw, Bf + gb);
        }
    };

    const uint32_t xorv   = (uint32_t)(lane & 6) << 3;
    const uint32_t aRowOff = (uint32_t)((wm + (lane & 15)) << 6);
    const uint32_t kaoff  = (uint32_t)((lane >> 4) << 4);
    const uint32_t bRowOff =
        (uint32_t)((wn + (lane & 7) + (((lane >> 4) & 1) << 3)) << 6);
    const uint32_t kboff  = (uint32_t)(((lane >> 3) & 1) << 4);

    float acc[2][8][4] = {};

    const int KCHUNKS = K >> 5;
    issue_stage(0); CP_COMMIT();

    for (int ch = 0; ch < KCHUNKS; ch++) {
        CP_WAIT(0);
        __syncthreads();
        if (ch + 1 < KCHUNKS) issue_stage(ch + 1);
        CP_COMMIT();

        const uint32_t buf = sb + (uint32_t)(ch & 1) * GQ_STAGE;
        const uint32_t aF = buf + aRowOff;
        const uint32_t bF = buf + 8192 + bRowOff;

        #pragma unroll
        for (int s = 0; s < 2; s++) {
            const uint32_t ca = ((uint32_t)(s << 5) + kaoff) ^ xorv;
            const uint32_t cb = ((uint32_t)(s << 5) + kboff) ^ xorv;
            uint32_t a4[2][4], b4[4][4];
            #pragma unroll
            for (int mt = 0; mt < 2; mt++)
                ldmx4(a4[mt], aF + (mt << 10) + ca);
            #pragma unroll
            for (int nt2 = 0; nt2 < 4; nt2++)
                ldmx4(b4[nt2], bF + (nt2 << 10) + cb);
            #pragma unroll
            for (int mt = 0; mt < 2; mt++)
                #pragma unroll
                for (int nt = 0; nt < 8; nt++)
                    mma_f16(acc[mt][nt], a4[mt],
                            b4[nt >> 1][(nt & 1) * 2],
                            b4[nt >> 1][(nt & 1) * 2 + 1]);
        }
    }

    // fused epilogue: head-major fp16; region 0=Q(scaled), 1=K, 2=V
    const int region = bn >> 10;
    const int cbase = (bn & 1023) + wn;
    const float qs = (region == 0) ? SCALE_LOG2 : 1.0f;
    __half* dst = (region == 0) ? Qf : (region == 1) ? Kf : Vf;
    #pragma unroll
    for (int mt = 0; mt < 2; mt++) {
        #pragma unroll
        for (int hr = 0; hr < 2; hr++) {
            const int r = bm + wm + mt * 16 + (lane >> 2) + hr * 8;
            const int bb = r >> 11, ss = r & (SQ - 1);
            #pragma unroll
            for (int nt = 0; nt < 8; nt++) {
                const int cc = cbase + nt * 8 + (lane & 3) * 2;
                const int h = cc >> 6, d = cc & 63;
                const size_t idx = (((size_t)(bb * NH + h) * SQ + ss) << 6) + d;
                float v0 = acc[mt][nt][hr * 2 + 0] * qs;
                float v1 = acc[mt][nt][hr * 2 + 1] * qs;
                __half2 hh = __floats2half2_rn(v0, v1);
                *(uint32_t*)(dst + idx) = *(uint32_t*)&hh;
            }
        }
    }
}

// ---- 2-pass GEMM for the out-projection (R8-proven, unchanged) ----------
#define G_STAGE 24576
#define GSM_TOTAL (2 * G_STAGE)

__global__ void __launch_bounds__(256, 2) gemm_mma(
    const __half* __restrict__ Ah, const __half* __restrict__ Al,
    const __half* __restrict__ Bf,
    float* __restrict__ C, int M, int N, int K) {
    extern __shared__ char smem[];
    const uint32_t sb = smem_to_u32(smem);
    const int tid = threadIdx.x;
    const int lane = tid & 31;
    const int wid = tid >> 5;
    const int bm = blockIdx.y * 128;
    const int bn = blockIdx.x * 128;
    const int wm = (wid >> 1) * 32;
    const int wn = (wid & 1) * 64;

    auto issue_stage = [&](int ch) {
        const int k0 = ch << 5;
        const uint32_t buf = sb + (uint32_t)(ch & 1) * G_STAGE;
        #pragma unroll
        for (int i = 0; i < 2; i++) {
            int lin = tid + (i << 8);
            int row = lin >> 2;
            int c4 = lin & 3;
            uint32_t off = (uint32_t)(row << 6) + (uint32_t)(c4 << 4);
            uint32_t sw = off ^ ((off >> 3) & 0x30);
            size_t ga = (size_t)(bm + row) * K + k0 + (c4 << 3);
            size_t gb = (size_t)(bn + row) * K + k0 + (c4 << 3);
            cp16(buf + sw,         Ah + ga);
            cp16(buf + 8192 + sw,  Al + ga);
            cp16(buf + 16384 + sw, Bf + gb);
        }
    };

    const uint32_t xorv   = (uint32_t)(lane & 6) << 3;
    const uint32_t aRowOff = (uint32_t)((wm + (lane & 15)) << 6);
    const uint32_t kaoff  = (uint32_t)((lane >> 4) << 4);
    const uint32_t bRowOff =
        (uint32_t)((wn + (lane & 7) + (((lane >> 4) & 1) << 3)) << 6);
    const uint32_t kboff  = (uint32_t)(((lane >> 3) & 1) << 4);

    float acc[2][8][4] = {};

    const int KCHUNKS = K >> 5;
    issue_stage(0); CP_COMMIT();

    for (int ch = 0; ch < KCHUNKS; ch++) {
        CP_WAIT(0);
        __syncthreads();
        if (ch + 1 < KCHUNKS) issue_stage(ch + 1);
        CP_COMMIT();

        const uint32_t buf = sb + (uint32_t)(ch & 1) * G_STAGE;
        const uint32_t aHi = buf + aRowOff;
        const uint32_t aLo = aHi + 8192;
        const uint32_t bF  = buf + 16384 + bRowOff;

        #pragma unroll
        for (int s = 0; s < 2; s++) {
            const uint32_t ca = ((uint32_t)(s << 5) + kaoff) ^ xorv;
            const uint32_t cb = ((uint32_t)(s << 5) + kboff) ^ xorv;
            uint32_t ah4[2][4], al4[2][4], b4[4][4];
            #pragma unroll
            for (int mt = 0; mt < 2; mt++) {
                ldmx4(ah4[mt], aHi + (mt << 10) + ca);
                ldmx4(al4[mt], aLo + (mt << 10) + ca);
            }
            #pragma unroll
            for (int nt2 = 0; nt2 < 4; nt2++)
                ldmx4(b4[nt2], bF + (nt2 << 10) + cb);
            #pragma unroll
            for (int mt = 0; mt < 2; mt++)
                #pragma unroll
                for (int nt = 0; nt < 8; nt++) {
                    const uint32_t b0 = b4[nt >> 1][(nt & 1) * 2];
                    const uint32_t b1 = b4[nt >> 1][(nt & 1) * 2 + 1];
                    mma_f16(acc[mt][nt], ah4[mt], b0, b1);
                    mma_f16(acc[mt][nt], al4[mt], b0, b1);
                }
        }
    }

    #pragma unroll
    for (int mt = 0; mt < 2; mt++) {
        const int r0 = bm + wm + mt * 16 + (lane >> 2);
        #pragma unroll
        for (int nt = 0; nt < 8; nt++) {
            const int c = bn + wn + nt * 8 + (lane & 3) * 2;
            float2 v0 = make_float2(acc[mt][nt][0], acc[mt][nt][1]);
            float2 v1 = make_float2(acc[mt][nt][2], acc[mt][nt][3]);
            *(float2*)&C[(size_t)r0 * N + c]       = v0;
            *(float2*)&C[(size_t)(r0 + 8) * N + c] = v1;
        }
    }
}

// ---------------------------------------------------------------------------
// fp16 tensor-core flash attention — R11: 1-pass S (Q plain), 1-pass PV.
// CTA = (b,h) x 128 q-rows; 8 warps x 16 rows; KV tiles of 64, double-buffer.
// smem 32KB: prologue stages Q at [0,16K) (loaded to regs), then the same
// space becomes KV stage 0; stage 1 at [16K,32K). 2 CTAs/SM.
// Output: fp16 hi/lo [b,s,1024] feeding the 2-pass out-proj.
// ---------------------------------------------------------------------------
#define A_STAGE 16384
#define ATT_SMEM 32768

__global__ void __launch_bounds__(256, 2) attn_mma(
    const __half* __restrict__ Qf,
    const __half* __restrict__ Kf, const __half* __restrict__ Vtf,
    __half* __restrict__ Oh, __half* __restrict__ Ol) {
    extern __shared__ char smem[];
    const uint32_t sb = smem_to_u32(smem);
    const int tid = threadIdx.x;
    const int lane = tid & 31;
    const int wid = tid >> 5;
    const int bh = blockIdx.y;
    const int q0 = blockIdx.x * 128;

    const size_t qbase = ((size_t)bh * SQ + q0) * HDIM;
    const size_t kbase = (size_t)bh * SQ * HDIM;
    const size_t vbase = (size_t)bh * HDIM * SQ;

    auto issue_q = [&]() {
        #pragma unroll
        for (int i = 0; i < 4; i++) {
            int lin = tid + (i << 8);
            int row = lin >> 3;
            int c8 = lin & 7;
            uint32_t off = (uint32_t)(row << 7) + (uint32_t)(c8 << 4);
            uint32_t sw = off ^ ((off >> 3) & 0x70);
            cp16(sb + sw, Qf + qbase + (size_t)row * HDIM + (c8 << 3));
        }
    };
    auto issue_kv = [&](int t) {
        const int kv0 = t << 6;
        const uint32_t stg = sb + (uint32_t)(t & 1) * A_STAGE;
        #pragma unroll
        for (int i = 0; i < 2; i++) {
            int lin = tid + (i << 8);
            int row = lin >> 3;
            int c8 = lin & 7;
            uint32_t off = (uint32_t)(row << 7) + (uint32_t)(c8 << 4);
            uint32_t sw = off ^ ((off >> 3) & 0x70);
            size_t gk = kbase + (size_t)(kv0 + row) * HDIM + (c8 << 3);
            size_t gv = vbase + (size_t)row * SQ + kv0 + (c8 << 3);
            cp16(stg + sw,        Kf + gk);
            cp16(stg + 8192 + sw, Vtf + gv);
        }
    };

    const uint32_t xorv = (uint32_t)(lane & 7) << 4;
    const uint32_t qRowOff = (uint32_t)(((wid << 4) + (lane & 15)) << 7);
    const uint32_t kaoff = (uint32_t)((lane >> 4) << 4);
    const uint32_t bRowOff =
        (uint32_t)(((lane & 7) + (((lane >> 4) & 1) << 3)) << 7);
    const uint32_t kboff = (uint32_t)(((lane >> 3) & 1) << 4);

    // ---- prologue: Q -> registers via stage-0 space ----
    issue_q(); CP_COMMIT();
    CP_WAIT(0);
    __syncthreads();

    uint32_t qh[4][4];
    #pragma unroll
    for (int kk = 0; kk < 4; kk++) {
        const uint32_t ca = ((uint32_t)(kk << 5) + kaoff) ^ xorv;
        ldmx4(qh[kk], sb + qRowOff + ca);
    }
    __syncthreads();            // all warps done reading Q staging

    issue_kv(0); CP_COMMIT();
    issue_kv(1); CP_COMMIT();
    CP_WAIT(1);
    __syncthreads();

    float m0 = -1e30f, m1 = -1e30f, l0 = 0.0f, l1 = 0.0f;
    float acc_o[8][4] = {};

    for (int t = 0; t < SQ / 64; t++) {
        const uint32_t stg = sb + (uint32_t)(t & 1) * A_STAGE;

        // ---- S = Q K^T (1 pass) ----
        float acc_s[8][4] = {};
        #pragma unroll
        for (int kk = 0; kk < 4; kk++) {
            const uint32_t cb = ((uint32_t)(kk << 5) + kboff) ^ xorv;
            #pragma unroll
            for (int nt2 = 0; nt2 < 4; nt2++) {
                uint32_t k4[4];
                ldmx4(k4, stg + bRowOff + (nt2 << 11) + cb);
                #pragma unroll
                for (int j = 0; j < 2; j++)
                    mma_f16(acc_s[2 * nt2 + j], qh[kk],
                            k4[j * 2], k4[j * 2 + 1]);
            }
        }

        // ---- online softmax (log2 domain) ----
        float mx0 = -1e30f, mx1 = -1e30f;
        #pragma unroll
        for (int nt = 0; nt < 8; nt++) {
            mx0 = fmaxf(mx0, fmaxf(acc_s[nt][0], acc_s[nt][1]));
            mx1 = fmaxf(mx1, fmaxf(acc_s[nt][2], acc_s[nt][3]));
        }
        mx0 = fmaxf(mx0, __shfl_xor_sync(0xffffffffu, mx0, 1));
        mx0 = fmaxf(mx0, __shfl_xor_sync(0xffffffffu, mx0, 2));
        mx1 = fmaxf(mx1, __shfl_xor_sync(0xffffffffu, mx1, 1));
        mx1 = fmaxf(mx1, __shfl_xor_sync(0xffffffffu, mx1, 2));
        const float mn0 = fmaxf(m0, mx0);
        const float mn1 = fmaxf(m1, mx1);
        const float a0 = ex2f(m0 - mn0);
        const float a1 = ex2f(m1 - mn1);
        m0 = mn0; m1 = mn1;
        float rs0 = 0.0f, rs1 = 0.0f;
        #pragma unroll
        for (int nt = 0; nt < 8; nt++) {
            float e0 = ex2f(acc_s[nt][0] - mn0);
            float e1 = ex2f(acc_s[nt][1] - mn0);
            float e2 = ex2f(acc_s[nt][2] - mn1);
            float e3 = ex2f(acc_s[nt][3] - mn1);
            rs0 += e0 + e1;
            rs1 += e2 + e3;
            __half2 h01 = __floats2half2_rn(e0, e1);
            __half2 h23 = __floats2half2_rn(e2, e3);
            acc_s[nt][0] = __uint_as_float(*(uint32_t*)&h01);
            acc_s[nt][1] = __uint_as_float(*(uint32_t*)&h23);
        }
        l0 = l0 * a0 + rs0;
        l1 = l1 * a1 + rs1;
        #pragma unroll
        for (int nt = 0; nt < 8; nt++) {
            acc_o[nt][0] *= a0; acc_o[nt][1] *= a0;
            acc_o[nt][2] *= a1; acc_o[nt][3] *= a1;
        }

        // ---- O += P V (1 pass; P fragments from acc_s bit slots) ----
        #pragma unroll
        for (int kk = 0; kk < 4; kk++) {
            uint32_t pf[4];
            pf[0] = __float_as_uint(acc_s[2 * kk][0]);
            pf[1] = __float_as_uint(acc_s[2 * kk][1]);
            pf[2] = __float_as_uint(acc_s[2 * kk + 1][0]);
            pf[3] = __float_as_uint(acc_s[2 * kk + 1][1]);
            const uint32_t cb = ((uint32_t)(kk << 5) + kboff) ^ xorv;
            #pragma unroll
            for (int nt2 = 0; nt2 < 4; nt2++) {
                uint32_t v4[4];
                ldmx4(v4, stg + 8192 + bRowOff + (nt2 << 11) + cb);
                #pragma unroll
                for (int j = 0; j < 2; j++)
                    mma_f16(acc_o[2 * nt2 + j], pf, v4[j * 2], v4[j * 2 + 1]);
            }
        }

        __syncthreads();
        if (t + 2 < SQ / 64) issue_kv(t + 2);
        CP_COMMIT();
        CP_WAIT(1);
        __syncthreads();
    }

    // ---- epilogue: normalize, fp16 split, store [b,s,1024] ----
    l0 += __shfl_xor_sync(0xffffffffu, l0, 1);
    l0 += __shfl_xor_sync(0xffffffffu, l0, 2);
    l1 += __shfl_xor_sync(0xffffffffu, l1, 1);
    l1 += __shfl_xor_sync(0xffffffffu, l1, 2);
    const float inv0 = 1.0f / l0;
    const float inv1 = 1.0f / l1;
    const int b = bh >> 4, h = bh & 15;
    const int srow = q0 + wid * 16 + (lane >> 2);
    const size_t ob0 = ((size_t)(b * SQ + srow)) * DH + h * HDIM + 2 * (lane & 3);
    const size_t ob1 = ob0 + 8 * DH;
    #pragma unroll
    for (int nt = 0; nt < 8; nt++) {
        float o0 = acc_o[nt][0] * inv0;
        float o1 = acc_o[nt][1] * inv0;
        float o2 = acc_o[nt][2] * inv1;
        float o3 = acc_o[nt][3] * inv1;
        __half2 h01 = __floats2half2_rn(o0, o1);
        __half2 h23 = __floats2half2_rn(o2, o3);
        float2 f01 = __half22float2(h01);
        float2 f23 = __half22float2(h23);
        __half2 l01 = __floats2half2_rn(o0 - f01.x, o1 - f01.y);
        __half2 l23 = __floats2half2_rn(o2 - f23.x, o3 - f23.y);
        *(uint32_t*)(Oh + ob0 + nt * 8) = *(uint32_t*)&h01;
        *(uint32_t*)(Ol + ob0 + nt * 8) = *(uint32_t*)&l01;
        *(uint32_t*)(Oh + ob1 + nt * 8) = *(uint32_t*)&h23;
        *(uint32_t*)(Ol + ob1 + nt * 8) = *(uint32_t*)&l23;
    }
}

// ---------------------------------------------------------------------------
extern "C" void kernel_launch(void* const* d_in, const int* in_sizes, int n_in,
                              void* d_out, int out_size) {
    const float* x     = (const float*)d_in[0];
    const float* w_qkv = (const float*)d_in[1];
    const float* w_out = (const float*)d_in[2];
    float* out = (float*)d_out;

    __half *xf, *wqf, *wof, *ah, *al;
    __half *Qf, *Kf, *Vf, *Vtf;
    cudaGetSymbolAddress((void**)&xf, g_xf);
    cudaGetSymbolAddress((void**)&wqf, g_wqf);
    cudaGetSymbolAddress((void**)&wof, g_wof);
    cudaGetSymbolAddress((void**)&ah, g_ah);
    cudaGetSymbolAddress((void**)&al, g_al);
    cudaGetSymbolAddress((void**)&Qf, g_Qf);
    cudaGetSymbolAddress((void**)&Kf, g_Kf);
    cudaGetSymbolAddress((void**)&Vf, g_Vf);
    cudaGetSymbolAddress((void**)&Vtf, g_Vtf);

    cudaFuncSetAttribute(gemm_qkv, cudaFuncAttributeMaxDynamicSharedMemorySize,
                         GQ_TOTAL);
    cudaFuncSetAttribute(gemm_mma, cudaFuncAttributeMaxDynamicSharedMemorySize,
                         GSM_TOTAL);
    cudaFuncSetAttribute(attn_mma, cudaFuncAttributeMaxDynamicSharedMemorySize,
                         ATT_SMEM);

    const int M = BZ * SQ;                 // 4096
    const int nX  = M * DH / 4;
    const int nWq = 3 * DH * DH / 4;
    const int nWo = DH * DH / 4;
    const int nTot = nX + nWq + nWo;

    // 0) input/weight conversion (single launch)
    prep_in<<<(nTot + 255) / 256, 256>>>((const float4*)x, (const float4*)w_qkv,
                                         (const float4*)w_out,
                                         (uint2*)xf, (uint2*)wqf, (uint2*)wof,
                                         nX, nWq, nWo);

    // 1) QKV projection (1-pass), fused epilogue -> head-major fp16 Q/K/V
    gemm_qkv<<<dim3(3 * DH / 128, M / 128), 256, GQ_TOTAL>>>(
        xf, wqf, Qf, Kf, Vf, M, 3 * DH, DH);

    // 2) V transpose -> [bh,64,s]
    transp_v<<<dim3(SQ / 64, BZ * NH), 256>>>(Vf, Vtf);

    // 3) attention -> fp16 hi/lo [b,s,1024]
    attn_mma<<<dim3(SQ / 128, BZ * NH), 256, ATT_SMEM>>>(Qf, Kf, Vtf, ah, al);

    // 4) output projection (2-pass) -> d_out (fp32)
    gemm_mma<<<dim3(DH / 128, M / 128), 256, GSM_TOTAL>>>(ah, al, wof, out,
                                                          M, DH, DH);
}